// round 4
// baseline (speedup 1.0000x reference)
#include <cuda_runtime.h>

#define BSZ   4
#define SEQ   4096
#define DIM   1024
#define NHEAD 16
#define HDIM  64
#define MROWS (BSZ * SEQ)          // 16384
#define QKVLD 3072
#define EPSV  1e-6f

// ---------------- scratch (static device globals; no allocation allowed) ----
__device__ float g_qkv[(size_t)MROWS * QKVLD];   // [M, 3072]: Q | K | V (phi applied to Q,K)
__device__ float g_attn[(size_t)MROWS * DIM];    // attention output before Wo
__device__ float g_kv[64 * 64 * 64];             // [B*H, 64, 64]
__device__ float g_z[64 * 64];                   // [B*H, 64]

// ---------------- zero the accumulation state ------------------------------
__global__ void zero_state() {
    int i = blockIdx.x * blockDim.x + threadIdx.x;
    if (i < 64 * 64 * 64) g_kv[i] = 0.f;
    if (i < 64 * 64)      g_z[i]  = 0.f;
}

// ---------------- fused QKV projection GEMM --------------------------------
// C[m, o] = sum_k x[m,k] * W[o,k] + b[o];  phi applied for o in [0,2048)
// Tile: BM=128, BN=128, BK=16, 256 threads, 8x8 per thread.
__global__ __launch_bounds__(256) void qkv_gemm(
    const float* __restrict__ x,
    const float* __restrict__ Wq, const float* __restrict__ bq,
    const float* __restrict__ Wk, const float* __restrict__ bk,
    const float* __restrict__ Wv, const float* __restrict__ bv)
{
    __shared__ float As[16][128];
    __shared__ float Bs[16][128];

    const int bn = blockIdx.x * 128;   // column in [0,3072)
    const int bm = blockIdx.y * 128;

    const float* W; const float* bias; int wbase;
    if (bn < 1024)      { W = Wq; bias = bq; wbase = bn; }
    else if (bn < 2048) { W = Wk; bias = bk; wbase = bn - 1024; }
    else                { W = Wv; bias = bv; wbase = bn - 2048; }

    const int tid = threadIdx.x;
    const int lr  = tid >> 2;            // 0..63
    const int lc  = (tid & 3) << 2;      // 0,4,8,12
    const int tx  = tid & 15;
    const int ty  = tid >> 4;

    float acc[8][8];
#pragma unroll
    for (int i = 0; i < 8; ++i)
#pragma unroll
        for (int j = 0; j < 8; ++j) acc[i][j] = 0.f;

    const float* Ag = x + (size_t)bm * DIM;
    const float* Bg = W + (size_t)wbase * DIM;

    for (int k0 = 0; k0 < DIM; k0 += 16) {
#pragma unroll
        for (int r = 0; r < 128; r += 64) {
            float4 a = *(const float4*)(Ag + (size_t)(lr + r) * DIM + k0 + lc);
            As[lc + 0][lr + r] = a.x; As[lc + 1][lr + r] = a.y;
            As[lc + 2][lr + r] = a.z; As[lc + 3][lr + r] = a.w;
            float4 w = *(const float4*)(Bg + (size_t)(lr + r) * DIM + k0 + lc);
            Bs[lc + 0][lr + r] = w.x; Bs[lc + 1][lr + r] = w.y;
            Bs[lc + 2][lr + r] = w.z; Bs[lc + 3][lr + r] = w.w;
        }
        __syncthreads();
#pragma unroll
        for (int k = 0; k < 16; ++k) {
            float av[8], bv_[8];
#pragma unroll
            for (int i = 0; i < 8; ++i) av[i]  = As[k][ty * 8 + i];
#pragma unroll
            for (int j = 0; j < 8; ++j) bv_[j] = Bs[k][tx * 8 + j];
#pragma unroll
            for (int i = 0; i < 8; ++i)
#pragma unroll
                for (int j = 0; j < 8; ++j) acc[i][j] += av[i] * bv_[j];
        }
        __syncthreads();
    }

    const bool isphi = (bn < 2048);
#pragma unroll
    for (int i = 0; i < 8; ++i) {
        const int m = bm + ty * 8 + i;
        float tmp[8];
#pragma unroll
        for (int j = 0; j < 8; ++j) {
            float v = acc[i][j] + bias[wbase + tx * 8 + j];
            if (isphi) v = (v > 0.f) ? (v + 1.f) : __expf(v);  // elu(v)+1
            tmp[j] = v;
        }
        float* op = g_qkv + (size_t)m * QKVLD + bn + tx * 8;
        *(float4*)op       = make_float4(tmp[0], tmp[1], tmp[2], tmp[3]);
        *(float4*)(op + 4) = make_float4(tmp[4], tmp[5], tmp[6], tmp[7]);
    }
}

// ---------------- KV state + Z reduction -----------------------------------
// KV[bh, d, e] = sum_n K[bh,n,d] * V[bh,n,e];  Z[bh,d] = sum_n K[bh,n,d]
// grid.x = 64 (b*h), grid.y = 8 (N split).  Atomic reduce into g_kv/g_z.
__global__ __launch_bounds__(256) void kv_state() {
    __shared__ float Ks[32][64];
    __shared__ float Vs[32][64];

    const int bh = blockIdx.x;
    const int b  = bh >> 4, h = bh & 15;
    const int n0 = blockIdx.y * (SEQ / 8);   // 512 rows per split

    const int tid = threadIdx.x;
    const int tx  = tid & 15;
    const int ty  = tid >> 4;
    const int lrr = tid >> 3;          // load row 0..31
    const int lcc = (tid & 7) * 8;     // load col

    float acc[4][4];
#pragma unroll
    for (int i = 0; i < 4; ++i)
#pragma unroll
        for (int j = 0; j < 4; ++j) acc[i][j] = 0.f;
    float zacc = 0.f;

    const float* Kbase = g_qkv + (size_t)(b * SEQ) * QKVLD + 1024 + h * HDIM;
    const float* Vbase = g_qkv + (size_t)(b * SEQ) * QKVLD + 2048 + h * HDIM;

    for (int n = n0; n < n0 + SEQ / 8; n += 32) {
        const float* kp = Kbase + (size_t)(n + lrr) * QKVLD + lcc;
        const float* vp = Vbase + (size_t)(n + lrr) * QKVLD + lcc;
        *(float4*)&Ks[lrr][lcc]     = *(const float4*)kp;
        *(float4*)&Ks[lrr][lcc + 4] = *(const float4*)(kp + 4);
        *(float4*)&Vs[lrr][lcc]     = *(const float4*)vp;
        *(float4*)&Vs[lrr][lcc + 4] = *(const float4*)(vp + 4);
        __syncthreads();
#pragma unroll
        for (int kk = 0; kk < 32; ++kk) {
            float rk[4], rv[4];
#pragma unroll
            for (int i = 0; i < 4; ++i) rk[i] = Ks[kk][ty + 16 * i];
#pragma unroll
            for (int j = 0; j < 4; ++j) rv[j] = Vs[kk][tx + 16 * j];
#pragma unroll
            for (int i = 0; i < 4; ++i)
#pragma unroll
                for (int j = 0; j < 4; ++j) acc[i][j] += rk[i] * rv[j];
        }
        if (tid < 64) {
#pragma unroll
            for (int kk = 0; kk < 32; ++kk) zacc += Ks[kk][tid];
        }
        __syncthreads();
    }

    float* kvp = g_kv + (size_t)bh * 4096;
#pragma unroll
    for (int i = 0; i < 4; ++i)
#pragma unroll
        for (int j = 0; j < 4; ++j)
            atomicAdd(&kvp[(ty + 16 * i) * 64 + (tx + 16 * j)], acc[i][j]);
    if (tid < 64) atomicAdd(&g_z[bh * 64 + tid], zacc);
}

// ---------------- attention epilogue ---------------------------------------
// out[bh,n,e] = (sum_d Q[bh,n,d]*KV[bh,d,e]) / (sum_d Q[bh,n,d]*Z[bh,d] + eps)
// grid.x = 64 (b*h), grid.y = 64 (tiles of 64 rows). 256 threads:
// tx = e-group (8 groups of 8 cols), ty = 32 row-lanes * 2 rows each.
__global__ __launch_bounds__(256) void attn_epilogue() {
    __shared__ float KVs[64 * 64];
    __shared__ float Qs[64][65];
    __shared__ float Zs[64];

    const int bh = blockIdx.x;
    const int b  = bh >> 4, h = bh & 15;
    const int n0 = blockIdx.y * 64;
    const int tid = threadIdx.x;

#pragma unroll
    for (int i = 0; i < 4; ++i) {
        int idx = (tid + i * 256) * 4;
        *(float4*)&KVs[idx] = *(const float4*)&g_kv[(size_t)bh * 4096 + idx];
    }
    if (tid < 64) Zs[tid] = g_z[bh * 64 + tid];
#pragma unroll
    for (int i = 0; i < 4; ++i) {
        int flat = (tid + i * 256) * 4;
        int r = flat >> 6, c = flat & 63;
        float4 q = *(const float4*)&g_qkv[(size_t)(b * SEQ + n0 + r) * QKVLD + h * HDIM + c];
        Qs[r][c] = q.x; Qs[r][c + 1] = q.y; Qs[r][c + 2] = q.z; Qs[r][c + 3] = q.w;
    }
    __syncthreads();

    const int tx = tid & 7;
    const int ty = tid >> 3;
    const int e0 = tx * 8;

    float acc[2][8] = {};
    float nrm[2]    = {};
#pragma unroll
    for (int d = 0; d < 64; ++d) {
        float4 k0 = *(const float4*)&KVs[d * 64 + e0];
        float4 k1 = *(const float4*)&KVs[d * 64 + e0 + 4];
        float kv8[8] = {k0.x, k0.y, k0.z, k0.w, k1.x, k1.y, k1.z, k1.w};
        float zd = Zs[d];
#pragma unroll
        for (int i = 0; i < 2; ++i) {
            float q = Qs[ty * 2 + i][d];
            nrm[i] += q * zd;
#pragma unroll
            for (int j = 0; j < 8; ++j) acc[i][j] += q * kv8[j];
        }
    }
#pragma unroll
    for (int i = 0; i < 2; ++i) {
        int n = n0 + ty * 2 + i;
        float inv = 1.f / (nrm[i] + EPSV);
        float* op = g_attn + (size_t)(b * SEQ + n) * DIM + h * HDIM + e0;
        float tmp[8];
#pragma unroll
        for (int j = 0; j < 8; ++j) tmp[j] = acc[i][j] * inv;
        *(float4*)op       = make_float4(tmp[0], tmp[1], tmp[2], tmp[3]);
        *(float4*)(op + 4) = make_float4(tmp[4], tmp[5], tmp[6], tmp[7]);
    }
}

// ---------------- output projection GEMM -----------------------------------
// out[m, o] = sum_k attn[m,k] * Wo[o,k] + bo[o]
__global__ __launch_bounds__(256) void out_gemm(
    const float* __restrict__ W, const float* __restrict__ bias,
    float* __restrict__ out)
{
    __shared__ float As[16][128];
    __shared__ float Bs[16][128];

    const int bn = blockIdx.x * 128;   // 0..1023
    const int bm = blockIdx.y * 128;

    const int tid = threadIdx.x;
    const int lr  = tid >> 2;
    const int lc  = (tid & 3) << 2;
    const int tx  = tid & 15;
    const int ty  = tid >> 4;

    float acc[8][8];
#pragma unroll
    for (int i = 0; i < 8; ++i)
#pragma unroll
        for (int j = 0; j < 8; ++j) acc[i][j] = 0.f;

    const float* Ag = g_attn + (size_t)bm * DIM;
    const float* Bg = W + (size_t)bn * DIM;

    for (int k0 = 0; k0 < DIM; k0 += 16) {
#pragma unroll
        for (int r = 0; r < 128; r += 64) {
            float4 a = *(const float4*)(Ag + (size_t)(lr + r) * DIM + k0 + lc);
            As[lc + 0][lr + r] = a.x; As[lc + 1][lr + r] = a.y;
            As[lc + 2][lr + r] = a.z; As[lc + 3][lr + r] = a.w;
            float4 w = *(const float4*)(Bg + (size_t)(lr + r) * DIM + k0 + lc);
            Bs[lc + 0][lr + r] = w.x; Bs[lc + 1][lr + r] = w.y;
            Bs[lc + 2][lr + r] = w.z; Bs[lc + 3][lr + r] = w.w;
        }
        __syncthreads();
#pragma unroll
        for (int k = 0; k < 16; ++k) {
            float av[8], bv_[8];
#pragma unroll
            for (int i = 0; i < 8; ++i) av[i]  = As[k][ty * 8 + i];
#pragma unroll
            for (int j = 0; j < 8; ++j) bv_[j] = Bs[k][tx * 8 + j];
#pragma unroll
            for (int i = 0; i < 8; ++i)
#pragma unroll
                for (int j = 0; j < 8; ++j) acc[i][j] += av[i] * bv_[j];
        }
        __syncthreads();
    }

#pragma unroll
    for (int i = 0; i < 8; ++i) {
        const int m = bm + ty * 8 + i;
        float tmp[8];
#pragma unroll
        for (int j = 0; j < 8; ++j)
            tmp[j] = acc[i][j] + bias[bn + tx * 8 + j];
        float* op = out + (size_t)m * DIM + bn + tx * 8;
        *(float4*)op       = make_float4(tmp[0], tmp[1], tmp[2], tmp[3]);
        *(float4*)(op + 4) = make_float4(tmp[4], tmp[5], tmp[6], tmp[7]);
    }
}

// ---------------- launch ----------------------------------------------------
extern "C" void kernel_launch(void* const* d_in, const int* in_sizes, int n_in,
                              void* d_out, int out_size) {
    const float* x  = (const float*)d_in[0];
    const float* Wq = (const float*)d_in[1];
    const float* bq = (const float*)d_in[2];
    const float* Wk = (const float*)d_in[3];
    const float* bk = (const float*)d_in[4];
    const float* Wv = (const float*)d_in[5];
    const float* bv = (const float*)d_in[6];
    const float* Wo = (const float*)d_in[7];
    const float* bo = (const float*)d_in[8];
    float* out = (float*)d_out;

    zero_state<<<1024, 256>>>();
    qkv_gemm<<<dim3(24, 128), 256>>>(x, Wq, bq, Wk, bk, Wv, bv);
    kv_state<<<dim3(64, 8), 256>>>();
    attn_epilogue<<<dim3(64, 64), 256>>>();
    out_gemm<<<dim3(8, 128), 256>>>(Wo, bo, out);
}

// round 5
// speedup vs baseline: 1.5813x; 1.5813x over previous
#include <cuda_runtime.h>
#include <mma.h>
using namespace nvcuda;

#define BSZ   4
#define SEQ   4096
#define DIM   1024
#define NHEAD 16
#define HDIM  64
#define MROWS (BSZ * SEQ)          // 16384
#define QKVLD 3072
#define EPSV  1e-6f

#define BM 128
#define BN 128
#define BK 32
#define KPAD 8                     // smem leading dim = BK + KPAD = 40

// ---------------- scratch (static device globals; no allocation allowed) ----
__device__ float g_qkv[(size_t)MROWS * QKVLD];   // [M, 3072]: Q | K | V (phi applied to Q,K)
__device__ float g_attn[(size_t)MROWS * DIM];    // attention output before Wo
__device__ float g_kv[64 * 64 * 64];             // [B*H, 64, 64]
__device__ float g_z[64 * 64];                   // [B*H, 64]

// ---------------- zero the accumulation state ------------------------------
__global__ void zero_state() {
    int i = blockIdx.x * blockDim.x + threadIdx.x;
    if (i < 64 * 64 * 64) g_kv[i] = 0.f;
    if (i < 64 * 64)      g_z[i]  = 0.f;
}

// ---------------- TF32 tensor-core GEMM tile -------------------------------
// C[m, n] = sum_k A[m,k] * W[n,k] + bias[n]   (optionally phi = elu+1)
// CTA tile 128x128, BK=32. 8 warps, each 64x32 (4 x 2 frags of 16x16x8).
__device__ __forceinline__ void gemm_tf32_tile(
    const float* __restrict__ Ag,    // A + bm*DIM  (row-major, ld = DIM)
    const float* __restrict__ Wg,    // W + wbase*DIM (row-major, ld = DIM)
    const float* __restrict__ bias,  // bias + wbase
    float* __restrict__ Cg,          // C + bm*ldc + bn
    int ldc, bool isphi)
{
    __shared__ float As[BM][BK + KPAD];
    __shared__ float Bs[BN][BK + KPAD];

    const int tid    = threadIdx.x;
    const int warpId = tid >> 5;
    const int lane   = tid & 31;
    const int warp_m = warpId & 1;    // 0..1 -> rows 64*warp_m
    const int warp_n = warpId >> 1;   // 0..3 -> cols 32*warp_n

    wmma::fragment<wmma::accumulator, 16, 16, 8, float> acc[4][2];
#pragma unroll
    for (int i = 0; i < 4; ++i)
#pragma unroll
        for (int j = 0; j < 2; ++j) wmma::fill_fragment(acc[i][j], 0.f);

    for (int k0 = 0; k0 < DIM; k0 += BK) {
        // stage 128x32 A and W tiles (256 thr x 4 float4 each per tile)
#pragma unroll
        for (int t = 0; t < 4; ++t) {
            int idx = tid + t * 256;          // 0..1023
            int row = idx >> 3;
            int col = (idx & 7) << 2;
            *(float4*)&As[row][col] = *(const float4*)(Ag + (size_t)row * DIM + k0 + col);
            *(float4*)&Bs[row][col] = *(const float4*)(Wg + (size_t)row * DIM + k0 + col);
        }
        __syncthreads();

#pragma unroll
        for (int ks = 0; ks < BK; ks += 8) {
            wmma::fragment<wmma::matrix_a, 16, 16, 8, wmma::precision::tf32, wmma::row_major> af[4];
            wmma::fragment<wmma::matrix_b, 16, 16, 8, wmma::precision::tf32, wmma::col_major> bf[2];
#pragma unroll
            for (int i = 0; i < 4; ++i) {
                wmma::load_matrix_sync(af[i], &As[warp_m * 64 + i * 16][ks], BK + KPAD);
#pragma unroll
                for (int e = 0; e < af[i].num_elements; ++e)
                    af[i].x[e] = wmma::__float_to_tf32(af[i].x[e]);
            }
#pragma unroll
            for (int j = 0; j < 2; ++j) {
                wmma::load_matrix_sync(bf[j], &Bs[warp_n * 32 + j * 16][ks], BK + KPAD);
#pragma unroll
                for (int e = 0; e < bf[j].num_elements; ++e)
                    bf[j].x[e] = wmma::__float_to_tf32(bf[j].x[e]);
            }
#pragma unroll
            for (int i = 0; i < 4; ++i)
#pragma unroll
                for (int j = 0; j < 2; ++j)
                    wmma::mma_sync(acc[i][j], af[i], bf[j], acc[i][j]);
        }
        __syncthreads();
    }

    // Epilogue: per-warp staging buffer carved out of As (free after last sync).
    float* Cst = &As[0][0] + warpId * 256;    // 16x16 per warp, disjoint regions
#pragma unroll
    for (int i = 0; i < 4; ++i) {
#pragma unroll
        for (int j = 0; j < 2; ++j) {
            wmma::store_matrix_sync(Cst, acc[i][j], 16, wmma::mem_row_major);
            __syncwarp();
            int r  = lane >> 1;
            int c  = (lane & 1) << 3;
            int gm = warp_m * 64 + i * 16 + r;
            int gn = warp_n * 32 + j * 16 + c;
            float tmp[8];
#pragma unroll
            for (int e = 0; e < 8; ++e) {
                float v = Cst[r * 16 + c + e] + bias[gn + e];
                if (isphi) v = (v > 0.f) ? (v + 1.f) : __expf(v);   // elu(v)+1
                tmp[e] = v;
            }
            float* op = Cg + (size_t)gm * ldc + gn;
            *(float4*)op       = make_float4(tmp[0], tmp[1], tmp[2], tmp[3]);
            *(float4*)(op + 4) = make_float4(tmp[4], tmp[5], tmp[6], tmp[7]);
            __syncwarp();
        }
    }
}

// ---------------- fused QKV projection (tensor core) ------------------------
__global__ __launch_bounds__(256, 2) void qkv_gemm_tc(
    const float* __restrict__ x,
    const float* __restrict__ Wq, const float* __restrict__ bq,
    const float* __restrict__ Wk, const float* __restrict__ bk,
    const float* __restrict__ Wv, const float* __restrict__ bv)
{
    const int bn = blockIdx.x * BN;   // 0..3071
    const int bm = blockIdx.y * BM;

    const float* W; const float* bias; int wbase;
    if (bn < 1024)      { W = Wq; bias = bq; wbase = bn; }
    else if (bn < 2048) { W = Wk; bias = bk; wbase = bn - 1024; }
    else                { W = Wv; bias = bv; wbase = bn - 2048; }

    gemm_tf32_tile(x + (size_t)bm * DIM,
                   W + (size_t)wbase * DIM,
                   bias + wbase,
                   g_qkv + (size_t)bm * QKVLD + bn,
                   QKVLD, bn < 2048);
}

// ---------------- output projection (tensor core) ---------------------------
__global__ __launch_bounds__(256, 2) void out_gemm_tc(
    const float* __restrict__ W, const float* __restrict__ bias,
    float* __restrict__ out)
{
    const int bn = blockIdx.x * BN;
    const int bm = blockIdx.y * BM;
    gemm_tf32_tile(g_attn + (size_t)bm * DIM,
                   W + (size_t)bn * DIM,
                   bias + bn,
                   out + (size_t)bm * DIM + bn,
                   DIM, false);
}

// ---------------- KV state + Z reduction -----------------------------------
// KV[bh, d, e] = sum_n K[bh,n,d] * V[bh,n,e];  Z[bh,d] = sum_n K[bh,n,d]
__global__ __launch_bounds__(256) void kv_state() {
    __shared__ float Ks[32][64];
    __shared__ float Vs[32][64];

    const int bh = blockIdx.x;
    const int b  = bh >> 4, h = bh & 15;
    const int n0 = blockIdx.y * (SEQ / 8);   // 512 rows per split

    const int tid = threadIdx.x;
    const int tx  = tid & 15;
    const int ty  = tid >> 4;
    const int lrr = tid >> 3;
    const int lcc = (tid & 7) * 8;

    float acc[4][4];
#pragma unroll
    for (int i = 0; i < 4; ++i)
#pragma unroll
        for (int j = 0; j < 4; ++j) acc[i][j] = 0.f;
    float zacc = 0.f;

    const float* Kbase = g_qkv + (size_t)(b * SEQ) * QKVLD + 1024 + h * HDIM;
    const float* Vbase = g_qkv + (size_t)(b * SEQ) * QKVLD + 2048 + h * HDIM;

    for (int n = n0; n < n0 + SEQ / 8; n += 32) {
        const float* kp = Kbase + (size_t)(n + lrr) * QKVLD + lcc;
        const float* vp = Vbase + (size_t)(n + lrr) * QKVLD + lcc;
        *(float4*)&Ks[lrr][lcc]     = *(const float4*)kp;
        *(float4*)&Ks[lrr][lcc + 4] = *(const float4*)(kp + 4);
        *(float4*)&Vs[lrr][lcc]     = *(const float4*)vp;
        *(float4*)&Vs[lrr][lcc + 4] = *(const float4*)(vp + 4);
        __syncthreads();
#pragma unroll
        for (int kk = 0; kk < 32; ++kk) {
            float rk[4], rv[4];
#pragma unroll
            for (int i = 0; i < 4; ++i) rk[i] = Ks[kk][ty + 16 * i];
#pragma unroll
            for (int j = 0; j < 4; ++j) rv[j] = Vs[kk][tx + 16 * j];
#pragma unroll
            for (int i = 0; i < 4; ++i)
#pragma unroll
                for (int j = 0; j < 4; ++j) acc[i][j] += rk[i] * rv[j];
        }
        if (tid < 64) {
#pragma unroll
            for (int kk = 0; kk < 32; ++kk) zacc += Ks[kk][tid];
        }
        __syncthreads();
    }

    float* kvp = g_kv + (size_t)bh * 4096;
#pragma unroll
    for (int i = 0; i < 4; ++i)
#pragma unroll
        for (int j = 0; j < 4; ++j)
            atomicAdd(&kvp[(ty + 16 * i) * 64 + (tx + 16 * j)], acc[i][j]);
    if (tid < 64) atomicAdd(&g_z[bh * 64 + tid], zacc);
}

// ---------------- attention epilogue ---------------------------------------
__global__ __launch_bounds__(256) void attn_epilogue() {
    __shared__ float KVs[64 * 64];
    __shared__ float Qs[64][65];
    __shared__ float Zs[64];

    const int bh = blockIdx.x;
    const int b  = bh >> 4, h = bh & 15;
    const int n0 = blockIdx.y * 64;
    const int tid = threadIdx.x;

#pragma unroll
    for (int i = 0; i < 4; ++i) {
        int idx = (tid + i * 256) * 4;
        *(float4*)&KVs[idx] = *(const float4*)&g_kv[(size_t)bh * 4096 + idx];
    }
    if (tid < 64) Zs[tid] = g_z[bh * 64 + tid];
#pragma unroll
    for (int i = 0; i < 4; ++i) {
        int flat = (tid + i * 256) * 4;
        int r = flat >> 6, c = flat & 63;
        float4 q = *(const float4*)&g_qkv[(size_t)(b * SEQ + n0 + r) * QKVLD + h * HDIM + c];
        Qs[r][c] = q.x; Qs[r][c + 1] = q.y; Qs[r][c + 2] = q.z; Qs[r][c + 3] = q.w;
    }
    __syncthreads();

    const int tx = tid & 7;
    const int ty = tid >> 3;
    const int e0 = tx * 8;

    float acc[2][8] = {};
    float nrm[2]    = {};
#pragma unroll
    for (int d = 0; d < 64; ++d) {
        float4 k0 = *(const float4*)&KVs[d * 64 + e0];
        float4 k1 = *(const float4*)&KVs[d * 64 + e0 + 4];
        float kv8[8] = {k0.x, k0.y, k0.z, k0.w, k1.x, k1.y, k1.z, k1.w};
        float zd = Zs[d];
#pragma unroll
        for (int i = 0; i < 2; ++i) {
            float q = Qs[ty * 2 + i][d];
            nrm[i] += q * zd;
#pragma unroll
            for (int j = 0; j < 8; ++j) acc[i][j] += q * kv8[j];
        }
    }
#pragma unroll
    for (int i = 0; i < 2; ++i) {
        int n = n0 + ty * 2 + i;
        float inv = 1.f / (nrm[i] + EPSV);
        float* op = g_attn + (size_t)(b * SEQ + n) * DIM + h * HDIM + e0;
        float tmp[8];
#pragma unroll
        for (int j = 0; j < 8; ++j) tmp[j] = acc[i][j] * inv;
        *(float4*)op       = make_float4(tmp[0], tmp[1], tmp[2], tmp[3]);
        *(float4*)(op + 4) = make_float4(tmp[4], tmp[5], tmp[6], tmp[7]);
    }
}

// ---------------- launch ----------------------------------------------------
extern "C" void kernel_launch(void* const* d_in, const int* in_sizes, int n_in,
                              void* d_out, int out_size) {
    const float* x  = (const float*)d_in[0];
    const float* Wq = (const float*)d_in[1];
    const float* bq = (const float*)d_in[2];
    const float* Wk = (const float*)d_in[3];
    const float* bk = (const float*)d_in[4];
    const float* Wv = (const float*)d_in[5];
    const float* bv = (const float*)d_in[6];
    const float* Wo = (const float*)d_in[7];
    const float* bo = (const float*)d_in[8];
    float* out = (float*)d_out;

    zero_state<<<1024, 256>>>();
    qkv_gemm_tc<<<dim3(24, 128), 256>>>(x, Wq, bq, Wk, bk, Wv, bv);
    kv_state<<<dim3(64, 8), 256>>>();
    attn_epilogue<<<dim3(64, 64), 256>>>();
    out_gemm_tc<<<dim3(8, 128), 256>>>(Wo, bo, out);
}

// round 6
// speedup vs baseline: 1.6939x; 1.0712x over previous
#include <cuda_runtime.h>
#include <mma.h>
using namespace nvcuda;

#define BSZ   4
#define SEQ   4096
#define DIM   1024
#define NHEAD 16
#define HDIM  64
#define MROWS (BSZ * SEQ)          // 16384
#define QKVLD 3072
#define EPSV  1e-6f

// GEMM tiling
#define BM   128
#define BN   256
#define BKT  32
#define LDK  40                    // BKT + 8 pad (floats)
#define NKT  (DIM / BKT)           // 32 k-tiles
#define GEMM_SMEM ((2 * (BM + BN) * LDK) * sizeof(float))   // 122880 B

// ---------------- scratch (static device globals; no allocation allowed) ----
__device__ float g_qkv[(size_t)MROWS * QKVLD];   // [M, 3072]: Q | K | V (phi applied to Q,K)
__device__ float g_attn[(size_t)MROWS * DIM];    // attention out (tf32-rounded) before Wo
__device__ float g_x[(size_t)MROWS * DIM];       // tf32-rounded input x
__device__ float g_w[4 * (size_t)DIM * DIM];     // tf32-rounded Wq|Wk|Wv|Wo
__device__ float g_kv[64 * 64 * 64];             // [B*H, 64, 64]
__device__ float g_z[64 * 64];                   // [B*H, 64]

// ---------------- helpers ---------------------------------------------------
__device__ __forceinline__ unsigned smem_u32(const void* p) {
    return (unsigned)__cvta_generic_to_shared(p);
}
__device__ __forceinline__ void cp_async16(unsigned dst, const float* src) {
    asm volatile("cp.async.cg.shared.global [%0], [%1], 16;\n" :: "r"(dst), "l"(src));
}
__device__ __forceinline__ void cp_commit() {
    asm volatile("cp.async.commit_group;\n" ::: "memory");
}
template <int N>
__device__ __forceinline__ void cp_wait() {
    asm volatile("cp.async.wait_group %0;\n" :: "n"(N) : "memory");
}

// ---------------- zero the accumulation state ------------------------------
__global__ void zero_state() {
    int i = blockIdx.x * blockDim.x + threadIdx.x;
    if (i < 64 * 64 * 64) g_kv[i] = 0.f;
    if (i < 64 * 64)      g_z[i]  = 0.f;
}

// ---------------- tf32 pre-rounding pass -----------------------------------
__global__ void round_tf32(const float* __restrict__ s, float* __restrict__ d, int n4) {
    int i = blockIdx.x * blockDim.x + threadIdx.x;
    if (i < n4) {
        float4 v = ((const float4*)s)[i];
        v.x = wmma::__float_to_tf32(v.x);
        v.y = wmma::__float_to_tf32(v.y);
        v.z = wmma::__float_to_tf32(v.z);
        v.w = wmma::__float_to_tf32(v.w);
        ((float4*)d)[i] = v;
    }
}

// ---------------- TF32 TC GEMM core (inputs pre-rounded) --------------------
// C[m,n] = sum_k A[m,k] * W[n,k] + bias[n]  (optional phi = elu+1)
// CTA 128x256, BK=32, cp.async 2-stage. 8 warps, each 64x64 (4x4 frags).
__device__ __forceinline__ void gemm_core(
    const float* __restrict__ Ag,    // A + bm*DIM  (ld = DIM)
    const float* __restrict__ Wg,    // W + tile-col-base*DIM (ld = DIM)
    const float* __restrict__ bias,  // bias + tile-col-base
    float* __restrict__ Cg,          // C + bm*ldc + bn
    int ldc, bool isphi, float* smem)
{
    float* sA = smem;                       // [2][BM][LDK]
    float* sB = smem + 2 * BM * LDK;        // [2][BN][LDK]

    const int tid    = threadIdx.x;
    const int warpId = tid >> 5;
    const int lane   = tid & 31;
    const int warp_m = warpId & 1;          // rows 64*warp_m
    const int warp_n = warpId >> 1;         // cols 64*warp_n

    // Per-thread staging coordinates (16B chunks)
    const int arow = tid >> 3;              // pattern base row for A
    const int acol = (tid & 7) << 2;        // col 0..28

    wmma::fragment<wmma::accumulator, 16, 16, 8, float> acc[4][4];
#pragma unroll
    for (int i = 0; i < 4; ++i)
#pragma unroll
        for (int j = 0; j < 4; ++j) wmma::fill_fragment(acc[i][j], 0.f);

    // --- stage loader: A (4 chunks) + B (8 chunks) per thread ---
    auto issue = [&](int t, int buf) {
        const int k0 = t * BKT;
        float* dA = sA + buf * BM * LDK;
        float* dB = sB + buf * BN * LDK;
#pragma unroll
        for (int r = 0; r < 4; ++r) {       // A: 128 rows
            int row = arow + r * 32;
            cp_async16(smem_u32(dA + row * LDK + acol),
                       Ag + (size_t)row * DIM + k0 + acol);
        }
#pragma unroll
        for (int r = 0; r < 8; ++r) {       // B: 256 rows
            int row = arow + r * 32;
            cp_async16(smem_u32(dB + row * LDK + acol),
                       Wg + (size_t)row * DIM + k0 + acol);
        }
        cp_commit();
    };

    issue(0, 0);

    for (int t = 0; t < NKT; ++t) {
        if (t + 1 < NKT) {
            issue(t + 1, (t + 1) & 1);
            cp_wait<1>();
        } else {
            cp_wait<0>();
        }
        __syncthreads();

        const float* As_ = sA + (t & 1) * BM * LDK + warp_m * 64 * LDK;
        const float* Bs_ = sB + (t & 1) * BN * LDK + warp_n * 64 * LDK;
#pragma unroll
        for (int ks = 0; ks < BKT; ks += 8) {
            wmma::fragment<wmma::matrix_a, 16, 16, 8, wmma::precision::tf32, wmma::row_major> af[4];
            wmma::fragment<wmma::matrix_b, 16, 16, 8, wmma::precision::tf32, wmma::col_major> bf[4];
#pragma unroll
            for (int i = 0; i < 4; ++i)
                wmma::load_matrix_sync(af[i], As_ + (i * 16) * LDK + ks, LDK);
#pragma unroll
            for (int j = 0; j < 4; ++j)
                wmma::load_matrix_sync(bf[j], Bs_ + (j * 16) * LDK + ks, LDK);
#pragma unroll
            for (int i = 0; i < 4; ++i)
#pragma unroll
                for (int j = 0; j < 4; ++j)
                    wmma::mma_sync(acc[i][j], af[i], bf[j], acc[i][j]);
        }
        __syncthreads();
    }

    // --- epilogue: per-warp 16x16 smem staging (smem free after last sync) ---
    float* Cst = smem + warpId * 256;
#pragma unroll
    for (int i = 0; i < 4; ++i) {
#pragma unroll
        for (int j = 0; j < 4; ++j) {
            wmma::store_matrix_sync(Cst, acc[i][j], 16, wmma::mem_row_major);
            __syncwarp();
            int r  = lane >> 1;
            int c  = (lane & 1) << 3;
            int gm = warp_m * 64 + i * 16 + r;
            int gn = warp_n * 64 + j * 16 + c;
            float tmp[8];
#pragma unroll
            for (int e = 0; e < 8; ++e) {
                float v = Cst[r * 16 + c + e] + bias[gn + e];
                if (isphi) v = (v > 0.f) ? (v + 1.f) : __expf(v);   // elu(v)+1
                tmp[e] = v;
            }
            float* op = Cg + (size_t)gm * ldc + gn;
            *(float4*)op       = make_float4(tmp[0], tmp[1], tmp[2], tmp[3]);
            *(float4*)(op + 4) = make_float4(tmp[4], tmp[5], tmp[6], tmp[7]);
            __syncwarp();
        }
    }
}

// ---------------- fused QKV projection (tensor core) ------------------------
__global__ __launch_bounds__(256, 1) void qkv_gemm_tc(
    const float* __restrict__ bq, const float* __restrict__ bk,
    const float* __restrict__ bv)
{
    extern __shared__ __align__(16) float smem[];
    const int bn = blockIdx.x * BN;     // 0..3071, tiles don't straddle Q/K/V
    const int bm = blockIdx.y * BM;
    const int sel   = bn >> 10;         // 0=Q, 1=K, 2=V
    const int wbase = bn & 1023;
    const float* bias = (sel == 0) ? bq : (sel == 1) ? bk : bv;

    gemm_core(g_x + (size_t)bm * DIM,
              g_w + (size_t)sel * DIM * DIM + (size_t)wbase * DIM,
              bias + wbase,
              g_qkv + (size_t)bm * QKVLD + bn,
              QKVLD, sel < 2, smem);
}

// ---------------- output projection (tensor core) ---------------------------
__global__ __launch_bounds__(256, 1) void out_gemm_tc(
    const float* __restrict__ bo, float* __restrict__ out)
{
    extern __shared__ __align__(16) float smem[];
    const int bn = blockIdx.x * BN;
    const int bm = blockIdx.y * BM;
    gemm_core(g_attn + (size_t)bm * DIM,
              g_w + 3 * (size_t)DIM * DIM + (size_t)bn * DIM,
              bo + bn,
              out + (size_t)bm * DIM + bn,
              DIM, false, smem);
}

// ---------------- KV state + Z reduction -----------------------------------
__global__ __launch_bounds__(256) void kv_state() {
    __shared__ float Ks[32][64];
    __shared__ float Vs[32][64];

    const int bh = blockIdx.x;
    const int b  = bh >> 4, h = bh & 15;
    const int n0 = blockIdx.y * (SEQ / 8);

    const int tid = threadIdx.x;
    const int tx  = tid & 15;
    const int ty  = tid >> 4;
    const int lrr = tid >> 3;
    const int lcc = (tid & 7) * 8;

    float acc[4][4];
#pragma unroll
    for (int i = 0; i < 4; ++i)
#pragma unroll
        for (int j = 0; j < 4; ++j) acc[i][j] = 0.f;
    float zacc = 0.f;

    const float* Kbase = g_qkv + (size_t)(b * SEQ) * QKVLD + 1024 + h * HDIM;
    const float* Vbase = g_qkv + (size_t)(b * SEQ) * QKVLD + 2048 + h * HDIM;

    for (int n = n0; n < n0 + SEQ / 8; n += 32) {
        const float* kp = Kbase + (size_t)(n + lrr) * QKVLD + lcc;
        const float* vp = Vbase + (size_t)(n + lrr) * QKVLD + lcc;
        *(float4*)&Ks[lrr][lcc]     = *(const float4*)kp;
        *(float4*)&Ks[lrr][lcc + 4] = *(const float4*)(kp + 4);
        *(float4*)&Vs[lrr][lcc]     = *(const float4*)vp;
        *(float4*)&Vs[lrr][lcc + 4] = *(const float4*)(vp + 4);
        __syncthreads();
#pragma unroll
        for (int kk = 0; kk < 32; ++kk) {
            float rk[4], rv[4];
#pragma unroll
            for (int i = 0; i < 4; ++i) rk[i] = Ks[kk][ty + 16 * i];
#pragma unroll
            for (int j = 0; j < 4; ++j) rv[j] = Vs[kk][tx + 16 * j];
#pragma unroll
            for (int i = 0; i < 4; ++i)
#pragma unroll
                for (int j = 0; j < 4; ++j) acc[i][j] += rk[i] * rv[j];
        }
        if (tid < 64) {
#pragma unroll
            for (int kk = 0; kk < 32; ++kk) zacc += Ks[kk][tid];
        }
        __syncthreads();
    }

    float* kvp = g_kv + (size_t)bh * 4096;
#pragma unroll
    for (int i = 0; i < 4; ++i)
#pragma unroll
        for (int j = 0; j < 4; ++j)
            atomicAdd(&kvp[(ty + 16 * i) * 64 + (tx + 16 * j)], acc[i][j]);
    if (tid < 64) atomicAdd(&g_z[bh * 64 + tid], zacc);
}

// ---------------- attention epilogue (writes tf32-rounded g_attn) ----------
__global__ __launch_bounds__(256) void attn_epilogue() {
    __shared__ float KVs[64 * 64];
    __shared__ float Qs[64][65];
    __shared__ float Zs[64];

    const int bh = blockIdx.x;
    const int b  = bh >> 4, h = bh & 15;
    const int n0 = blockIdx.y * 64;
    const int tid = threadIdx.x;

#pragma unroll
    for (int i = 0; i < 4; ++i) {
        int idx = (tid + i * 256) * 4;
        *(float4*)&KVs[idx] = *(const float4*)&g_kv[(size_t)bh * 4096 + idx];
    }
    if (tid < 64) Zs[tid] = g_z[bh * 64 + tid];
#pragma unroll
    for (int i = 0; i < 4; ++i) {
        int flat = (tid + i * 256) * 4;
        int r = flat >> 6, c = flat & 63;
        float4 q = *(const float4*)&g_qkv[(size_t)(b * SEQ + n0 + r) * QKVLD + h * HDIM + c];
        Qs[r][c] = q.x; Qs[r][c + 1] = q.y; Qs[r][c + 2] = q.z; Qs[r][c + 3] = q.w;
    }
    __syncthreads();

    const int tx = tid & 7;
    const int ty = tid >> 3;
    const int e0 = tx * 8;

    float acc[2][8] = {};
    float nrm[2]    = {};
#pragma unroll
    for (int d = 0; d < 64; ++d) {
        float4 k0 = *(const float4*)&KVs[d * 64 + e0];
        float4 k1 = *(const float4*)&KVs[d * 64 + e0 + 4];
        float kv8[8] = {k0.x, k0.y, k0.z, k0.w, k1.x, k1.y, k1.z, k1.w};
        float zd = Zs[d];
#pragma unroll
        for (int i = 0; i < 2; ++i) {
            float q = Qs[ty * 2 + i][d];
            nrm[i] += q * zd;
#pragma unroll
            for (int j = 0; j < 8; ++j) acc[i][j] += q * kv8[j];
        }
    }
#pragma unroll
    for (int i = 0; i < 2; ++i) {
        int n = n0 + ty * 2 + i;
        float inv = 1.f / (nrm[i] + EPSV);
        float* op = g_attn + (size_t)(b * SEQ + n) * DIM + h * HDIM + e0;
        float tmp[8];
#pragma unroll
        for (int j = 0; j < 8; ++j)
            tmp[j] = wmma::__float_to_tf32(acc[i][j] * inv);   // pre-round for TC
        *(float4*)op       = make_float4(tmp[0], tmp[1], tmp[2], tmp[3]);
        *(float4*)(op + 4) = make_float4(tmp[4], tmp[5], tmp[6], tmp[7]);
    }
}

// ---------------- launch ----------------------------------------------------
extern "C" void kernel_launch(void* const* d_in, const int* in_sizes, int n_in,
                              void* d_out, int out_size) {
    const float* x  = (const float*)d_in[0];
    const float* Wq = (const float*)d_in[1];
    const float* bq = (const float*)d_in[2];
    const float* Wk = (const float*)d_in[3];
    const float* bk = (const float*)d_in[4];
    const float* Wv = (const float*)d_in[5];
    const float* bv = (const float*)d_in[6];
    const float* Wo = (const float*)d_in[7];
    const float* bo = (const float*)d_in[8];
    float* out = (float*)d_out;

    cudaFuncSetAttribute(qkv_gemm_tc, cudaFuncAttributeMaxDynamicSharedMemorySize, GEMM_SMEM);
    cudaFuncSetAttribute(out_gemm_tc, cudaFuncAttributeMaxDynamicSharedMemorySize, GEMM_SMEM);

    float* gx; cudaGetSymbolAddress((void**)&gx, g_x);
    float* gw; cudaGetSymbolAddress((void**)&gw, g_w);

    zero_state<<<1024, 256>>>();

    // tf32 pre-rounding: x and the four weight matrices
    round_tf32<<<(MROWS * DIM / 4 + 255) / 256, 256>>>(x,  gx, MROWS * DIM / 4);
    round_tf32<<<(DIM * DIM / 4 + 255) / 256, 256>>>(Wq, gw + 0 * (size_t)DIM * DIM, DIM * DIM / 4);
    round_tf32<<<(DIM * DIM / 4 + 255) / 256, 256>>>(Wk, gw + 1 * (size_t)DIM * DIM, DIM * DIM / 4);
    round_tf32<<<(DIM * DIM / 4 + 255) / 256, 256>>>(Wv, gw + 2 * (size_t)DIM * DIM, DIM * DIM / 4);
    round_tf32<<<(DIM * DIM / 4 + 255) / 256, 256>>>(Wo, gw + 3 * (size_t)DIM * DIM, DIM * DIM / 4);

    qkv_gemm_tc<<<dim3(QKVLD / BN, MROWS / BM), 256, GEMM_SMEM>>>(bq, bk, bv);
    kv_state<<<dim3(64, 8), 256>>>();
    attn_epilogue<<<dim3(64, 64), 256>>>();
    out_gemm_tc<<<dim3(DIM / BN, MROWS / BM), 256, GEMM_SMEM>>>(bo, out);
}

// round 9
// speedup vs baseline: 4.1666x; 2.4597x over previous
#include <cuda_runtime.h>
#include <cuda_fp16.h>
#include <cstdint>

#define BSZ   4
#define SEQ   4096
#define DIM   1024
#define NHEAD 16
#define HDIM  64
#define MROWS (BSZ * SEQ)
#define QKVLD 3072
#define EPSV  1e-6f

// ---- fp16 HMMA GEMM tiling -------------------------------------------------
#define BM 128
#define BN 256
#define BK 32                       // halves per k-chunk
#define NCH (DIM / BK)              // 32 chunks
#define LDHB 80u                    // smem row pitch in bytes (40 halves)
#define A_BYTES 10240u              // 128 rows * 80B
#define B_BYTES 20480u              // 256 rows * 80B
#define STGB (A_BYTES + B_BYTES)    // 30720B per stage
#define GEMM_SMEM (3 * STGB)        // 92160B

// ---------------- scratch (static device globals) ---------------------------
__device__ float  g_qkv[(size_t)MROWS * QKVLD];   // Q|K|V fp32 (phi applied to Q,K)
__device__ __half g_attnh[(size_t)MROWS * DIM];   // attention out (half) for Wo GEMM
__device__ __half g_xh[(size_t)MROWS * DIM];      // x in half
__device__ __half g_wh[4 * (size_t)DIM * DIM];    // Wq|Wk|Wv|Wo in half
__device__ float  g_kv[64 * 64 * 64];
__device__ float  g_z[64 * 64];

// ---------------- PTX helpers ------------------------------------------------
__device__ __forceinline__ uint32_t smem_u32(const void* p) {
    return (uint32_t)__cvta_generic_to_shared(p);
}

#define CP_ASYNC16(dst, src) \
    asm volatile("cp.async.cg.shared.global [%0], [%1], 16;" :: "r"(dst), "l"(src))
#define CP_COMMIT() asm volatile("cp.async.commit_group;" ::: "memory")
#define CP_WAIT_1() asm volatile("cp.async.wait_group 1;" ::: "memory")
#define CP_WAIT_0() asm volatile("cp.async.wait_group 0;" ::: "memory")

#define LDSM4(r0, r1, r2, r3, addr) \
    asm volatile("ldmatrix.sync.aligned.m8n8.x4.shared.b16 {%0,%1,%2,%3}, [%4];" \
                 : "=r"(r0), "=r"(r1), "=r"(r2), "=r"(r3) : "r"(addr))

#define MMA16816(d, a, b) \
    asm volatile("mma.sync.aligned.m16n8k16.row.col.f32.f16.f16.f32 " \
                 "{%0,%1,%2,%3}, {%4,%5,%6,%7}, {%8,%9}, {%0,%1,%2,%3};" \
                 : "+f"((d)[0]), "+f"((d)[1]), "+f"((d)[2]), "+f"((d)[3]) \
                 : "r"((a)[0]), "r"((a)[1]), "r"((a)[2]), "r"((a)[3]), \
                   "r"((b)[0]), "r"((b)[1]))

// ---------------- zero the accumulation state ------------------------------
__global__ void zero_state() {
    int i = blockIdx.x * blockDim.x + threadIdx.x;
    if (i < 64 * 64 * 64) g_kv[i] = 0.f;
    if (i < 64 * 64)      g_z[i]  = 0.f;
}

// ---------------- fp32 -> fp16 conversion ----------------------------------
__global__ void to_half4(const float* __restrict__ s, __half* __restrict__ d, int n4) {
    int i = blockIdx.x * blockDim.x + threadIdx.x;
    if (i < n4) {
        float4 v = ((const float4*)s)[i];
        __half2 h0 = __floats2half2_rn(v.x, v.y);
        __half2 h1 = __floats2half2_rn(v.z, v.w);
        ((__half2*)d)[2 * i]     = h0;
        ((__half2*)d)[2 * i + 1] = h1;
    }
}

// ---------------- stage loader (cp.async) -----------------------------------
// A: 128 rows x 32 halves (512 x 16B segs), B: 256 rows (1024 segs). 6 per thread.
__device__ __forceinline__ void load_stage_h(
    uint32_t sb, int chunk,
    const __half* __restrict__ Ag, const __half* __restrict__ Wg, int tid)
{
    const int k0 = chunk * BK;
#pragma unroll
    for (int i = 0; i < 6; ++i) {
        int s = tid + i * 256;             // 0..1535
        int isB = (s >= 512) ? 1 : 0;
        int t2 = isB ? (s - 512) : s;
        int row = t2 >> 2;
        int seg = t2 & 3;
        const __half* src = (isB ? Wg : Ag) + (size_t)row * DIM + k0 + seg * 8;
        uint32_t dst = sb + (isB ? A_BYTES : 0u) + (uint32_t)row * LDHB + (uint32_t)seg * 16u;
        CP_ASYNC16(dst, src);
    }
    CP_COMMIT();
}

// ---------------- fp16 HMMA GEMM core ---------------------------------------
// C[128,256]: C[m,n] = sum_k A[m,k]*W[n,k] + bias[n]   (optional phi = elu+1)
__device__ __forceinline__ void gemm_h_core(
    const __half* __restrict__ Ag, const __half* __restrict__ Wg,
    const float* __restrict__ bias, float* __restrict__ Cg,
    int ldc, int isphi, __half* hsm)
{
    const int tid  = threadIdx.x;
    const int wid  = tid >> 5;
    const int lane = tid & 31;
    const int wm   = wid & 1;           // 0..1 -> rows 64*wm
    const int wn   = wid >> 1;          // 0..3 -> cols 64*wn

    const uint32_t sbase = smem_u32(hsm);

    // per-lane ldmatrix coordinates
    const int a_r = lane & 15;
    const int a_c = (lane >> 4) * 8;                       // halves
    const int b_r = (lane & 7) + ((lane >> 4) & 1) * 8;
    const int b_c = ((lane >> 3) & 1) * 8;                 // halves

    float acc[4][8][4];
#pragma unroll
    for (int i = 0; i < 4; ++i)
#pragma unroll
        for (int j = 0; j < 8; ++j)
#pragma unroll
            for (int e = 0; e < 4; ++e) acc[i][j][e] = 0.f;

    // prologue: 2 stages in flight
    load_stage_h(sbase + 0u * STGB, 0, Ag, Wg, tid);
    load_stage_h(sbase + 1u * STGB, 1, Ag, Wg, tid);

    for (int c = 0; c < NCH; ++c) {
        if (c + 2 < NCH) { CP_WAIT_1(); } else { CP_WAIT_0(); }
        __syncthreads();
        if (c + 2 < NCH)
            load_stage_h(sbase + (uint32_t)((c + 2) % 3) * STGB, c + 2, Ag, Wg, tid);

        const uint32_t As = sbase + (uint32_t)(c % 3) * STGB;
        const uint32_t Bs = As + A_BYTES;

#pragma unroll
        for (int ks = 0; ks < BK; ks += 16) {
            uint32_t a[4][4];
#pragma unroll
            for (int mb = 0; mb < 4; ++mb) {
                uint32_t addr = As + (uint32_t)(wm * 64 + mb * 16 + a_r) * LDHB
                              + (uint32_t)(ks + a_c) * 2u;
                LDSM4(a[mb][0], a[mb][1], a[mb][2], a[mb][3], addr);
            }
            uint32_t b[8][2];
#pragma unroll
            for (int p = 0; p < 4; ++p) {
                uint32_t addr = Bs + (uint32_t)(wn * 64 + p * 16 + b_r) * LDHB
                              + (uint32_t)(ks + b_c) * 2u;
                uint32_t r0, r1, r2, r3;
                LDSM4(r0, r1, r2, r3, addr);
                b[2 * p][0] = r0; b[2 * p][1] = r1;
                b[2 * p + 1][0] = r2; b[2 * p + 1][1] = r3;
            }
#pragma unroll
            for (int mb = 0; mb < 4; ++mb)
#pragma unroll
                for (int nb = 0; nb < 8; ++nb)
                    MMA16816(acc[mb][nb], a[mb], b[nb]);
        }
        __syncthreads();
    }

    // epilogue: direct float2 stores, bias + optional phi
    const int g = lane >> 2;
    const int t = lane & 3;
#pragma unroll
    for (int mb = 0; mb < 4; ++mb) {
#pragma unroll
        for (int nb = 0; nb < 8; ++nb) {
            int col  = wn * 64 + nb * 8 + 2 * t;
            float b0 = bias[col];
            float b1 = bias[col + 1];
            int row0 = wm * 64 + mb * 16 + g;
            float v0 = acc[mb][nb][0] + b0;
            float v1 = acc[mb][nb][1] + b1;
            float v2 = acc[mb][nb][2] + b0;
            float v3 = acc[mb][nb][3] + b1;
            if (isphi) {
                v0 = (v0 > 0.f) ? (v0 + 1.f) : __expf(v0);
                v1 = (v1 > 0.f) ? (v1 + 1.f) : __expf(v1);
                v2 = (v2 > 0.f) ? (v2 + 1.f) : __expf(v2);
                v3 = (v3 > 0.f) ? (v3 + 1.f) : __expf(v3);
            }
            *(float2*)(Cg + (size_t)row0 * ldc + col)       = make_float2(v0, v1);
            *(float2*)(Cg + (size_t)(row0 + 8) * ldc + col) = make_float2(v2, v3);
        }
    }
}

// ---------------- GEMM entry points -----------------------------------------
__global__ __launch_bounds__(256, 1) void qkv_gemm_h(
    const float* __restrict__ bq, const float* __restrict__ bk,
    const float* __restrict__ bv)
{
    extern __shared__ __align__(16) __half hsm[];
    const int bn = blockIdx.x * BN;    // 256 | 1024: no Q/K/V straddle
    const int bm = blockIdx.y * BM;
    const int sel   = bn >> 10;        // 0=Q 1=K 2=V
    const int wbase = bn & 1023;
    const float* bias = (sel == 0) ? bq : ((sel == 1) ? bk : bv);

    gemm_h_core(g_xh + (size_t)bm * DIM,
                g_wh + (size_t)sel * DIM * DIM + (size_t)wbase * DIM,
                bias + wbase,
                g_qkv + (size_t)bm * QKVLD + bn,
                QKVLD, (sel < 2) ? 1 : 0, hsm);
}

__global__ __launch_bounds__(256, 1) void out_gemm_h(
    const float* __restrict__ bo, float* __restrict__ out)
{
    extern __shared__ __align__(16) __half hsm[];
    const int bn = blockIdx.x * BN;
    const int bm = blockIdx.y * BM;

    gemm_h_core(g_attnh + (size_t)bm * DIM,
                g_wh + 3 * (size_t)DIM * DIM + (size_t)bn * DIM,
                bo + bn,
                out + (size_t)bm * DIM + bn,
                DIM, 0, hsm);
}

// ---------------- KV state + Z reduction -----------------------------------
__global__ __launch_bounds__(256) void kv_state() {
    __shared__ float Ks[32][64];
    __shared__ float Vs[32][64];

    const int bh = blockIdx.x;
    const int b  = bh >> 4;
    const int h  = bh & 15;
    const int n0 = blockIdx.y * (SEQ / 8);

    const int tid = threadIdx.x;
    const int tx  = tid & 15;
    const int ty  = tid >> 4;
    const int lrr = tid >> 3;
    const int lcc = (tid & 7) * 8;

    float acc[4][4];
#pragma unroll
    for (int i = 0; i < 4; ++i) {
#pragma unroll
        for (int j = 0; j < 4; ++j) acc[i][j] = 0.f;
    }
    float zacc = 0.f;

    const float* Kbase = g_qkv + (size_t)(b * SEQ) * QKVLD + 1024 + h * HDIM;
    const float* Vbase = g_qkv + (size_t)(b * SEQ) * QKVLD + 2048 + h * HDIM;

    for (int n = n0; n < n0 + SEQ / 8; n += 32) {
        const float* kp = Kbase + (size_t)(n + lrr) * QKVLD + lcc;
        const float* vp = Vbase + (size_t)(n + lrr) * QKVLD + lcc;
        *(float4*)&Ks[lrr][lcc]     = *(const float4*)kp;
        *(float4*)&Ks[lrr][lcc + 4] = *(const float4*)(kp + 4);
        *(float4*)&Vs[lrr][lcc]     = *(const float4*)vp;
        *(float4*)&Vs[lrr][lcc + 4] = *(const float4*)(vp + 4);
        __syncthreads();
#pragma unroll
        for (int kk = 0; kk < 32; ++kk) {
            float rk[4];
            float rv[4];
#pragma unroll
            for (int i = 0; i < 4; ++i) rk[i] = Ks[kk][ty + 16 * i];
#pragma unroll
            for (int j = 0; j < 4; ++j) rv[j] = Vs[kk][tx + 16 * j];
#pragma unroll
            for (int i = 0; i < 4; ++i) {
#pragma unroll
                for (int j = 0; j < 4; ++j) acc[i][j] += rk[i] * rv[j];
            }
        }
        if (tid < 64) {
#pragma unroll
            for (int kk = 0; kk < 32; ++kk) zacc += Ks[kk][tid];
        }
        __syncthreads();
    }

    float* kvp = g_kv + (size_t)bh * 4096;
#pragma unroll
    for (int i = 0; i < 4; ++i) {
#pragma unroll
        for (int j = 0; j < 4; ++j) {
            atomicAdd(&kvp[(ty + 16 * i) * 64 + (tx + 16 * j)], acc[i][j]);
        }
    }
    if (tid < 64) atomicAdd(&g_z[bh * 64 + tid], zacc);
}

// ---------------- attention epilogue (writes half g_attnh) ------------------
__global__ __launch_bounds__(256) void attn_epilogue() {
    __shared__ float KVs[64 * 64];
    __shared__ float Qs[64][65];
    __shared__ float Zs[64];

    const int bh = blockIdx.x;
    const int b  = bh >> 4;
    const int h  = bh & 15;
    const int n0 = blockIdx.y * 64;
    const int tid = threadIdx.x;

#pragma unroll
    for (int i = 0; i < 4; ++i) {
        int idx = (tid + i * 256) * 4;
        *(float4*)&KVs[idx] = *(const float4*)&g_kv[(size_t)bh * 4096 + idx];
    }
    if (tid < 64) Zs[tid] = g_z[bh * 64 + tid];
#pragma unroll
    for (int i = 0; i < 4; ++i) {
        int flat = (tid + i * 256) * 4;
        int r = flat >> 6;
        int c = flat & 63;
        float4 q = *(const float4*)&g_qkv[(size_t)(b * SEQ + n0 + r) * QKVLD + h * HDIM + c];
        Qs[r][c] = q.x; Qs[r][c + 1] = q.y; Qs[r][c + 2] = q.z; Qs[r][c + 3] = q.w;
    }
    __syncthreads();

    const int tx = tid & 7;
    const int ty = tid >> 3;
    const int e0 = tx * 8;

    float acc[2][8] = {};
    float nrm[2]    = {};
#pragma unroll
    for (int d = 0; d < 64; ++d) {
        float4 k0 = *(const float4*)&KVs[d * 64 + e0];
        float4 k1 = *(const float4*)&KVs[d * 64 + e0 + 4];
        float kv8[8] = {k0.x, k0.y, k0.z, k0.w, k1.x, k1.y, k1.z, k1.w};
        float zd = Zs[d];
#pragma unroll
        for (int i = 0; i < 2; ++i) {
            float q = Qs[ty * 2 + i][d];
            nrm[i] += q * zd;
#pragma unroll
            for (int j = 0; j < 8; ++j) acc[i][j] += q * kv8[j];
        }
    }
#pragma unroll
    for (int i = 0; i < 2; ++i) {
        int n = n0 + ty * 2 + i;
        float inv = 1.f / (nrm[i] + EPSV);
        __half* op = g_attnh + (size_t)(b * SEQ + n) * DIM + h * HDIM + e0;
        __half2 h0 = __floats2half2_rn(acc[i][0] * inv, acc[i][1] * inv);
        __half2 h1 = __floats2half2_rn(acc[i][2] * inv, acc[i][3] * inv);
        __half2 h2 = __floats2half2_rn(acc[i][4] * inv, acc[i][5] * inv);
        __half2 h3 = __floats2half2_rn(acc[i][6] * inv, acc[i][7] * inv);
        uint4 u;
        u.x = *(uint32_t*)&h0;
        u.y = *(uint32_t*)&h1;
        u.z = *(uint32_t*)&h2;
        u.w = *(uint32_t*)&h3;
        *(uint4*)op = u;
    }
}

// ---------------- launch ----------------------------------------------------
extern "C" void kernel_launch(void* const* d_in, const int* in_sizes, int n_in,
                              void* d_out, int out_size) {
    const float* x  = (const float*)d_in[0];
    const float* Wq = (const float*)d_in[1];
    const float* bq = (const float*)d_in[2];
    const float* Wk = (const float*)d_in[3];
    const float* bk = (const float*)d_in[4];
    const float* Wv = (const float*)d_in[5];
    const float* bv = (const float*)d_in[6];
    const float* Wo = (const float*)d_in[7];
    const float* bo = (const float*)d_in[8];
    float* out = (float*)d_out;

    cudaFuncSetAttribute(qkv_gemm_h, cudaFuncAttributeMaxDynamicSharedMemorySize, GEMM_SMEM);
    cudaFuncSetAttribute(out_gemm_h, cudaFuncAttributeMaxDynamicSharedMemorySize, GEMM_SMEM);

    __half* gxh = 0;
    __half* gwh = 0;
    cudaGetSymbolAddress((void**)&gxh, g_xh);
    cudaGetSymbolAddress((void**)&gwh, g_wh);

    zero_state<<<1024, 256>>>();

    to_half4<<<(MROWS * DIM / 4 + 255) / 256, 256>>>(x, gxh, MROWS * DIM / 4);
    to_half4<<<(DIM * DIM / 4 + 255) / 256, 256>>>(Wq, gwh + 0 * (size_t)DIM * DIM, DIM * DIM / 4);
    to_half4<<<(DIM * DIM / 4 + 255) / 256, 256>>>(Wk, gwh + 1 * (size_t)DIM * DIM, DIM * DIM / 4);
    to_half4<<<(DIM * DIM / 4 + 255) / 256, 256>>>(Wv, gwh + 2 * (size_t)DIM * DIM, DIM * DIM / 4);
    to_half4<<<(DIM * DIM / 4 + 255) / 256, 256>>>(Wo, gwh + 3 * (size_t)DIM * DIM, DIM * DIM / 4);

    qkv_gemm_h<<<dim3(QKVLD / BN, MROWS / BM), 256, GEMM_SMEM>>>(bq, bk, bv);
    kv_state<<<dim3(64, 8), 256>>>();
    attn_epilogue<<<dim3(64, 64), 256>>>();
    out_gemm_h<<<dim3(DIM / BN, MROWS / BM), 256, GEMM_SMEM>>>(bo, out);
}

// round 10
// speedup vs baseline: 5.3987x; 1.2957x over previous
#include <cuda_runtime.h>
#include <cuda_fp16.h>
#include <cstdint>

#define BSZ   4
#define SEQ   4096
#define DIM   1024
#define NHEAD 16
#define HDIM  64
#define MROWS (BSZ * SEQ)
#define QKVLD 3072
#define EPSV  1e-6f

// ---- fp16 HMMA GEMM tiling: 128x128 CTA tile, 2 CTAs/SM ---------------------
#define BM 128
#define BN 128
#define BK 32                       // halves per k-chunk
#define NCH (DIM / BK)              // 32 chunks
#define LDHB 80u                    // smem row pitch bytes (40 halves)
#define A_BYTES 10240u              // 128 rows * 80B
#define STGB 20480u                 // A + B per stage
#define GEMM_SMEM (3 * STGB)        // 61440B

// ---------------- scratch (static device globals) ---------------------------
__device__ float  g_qkv[(size_t)MROWS * QKVLD];   // Q|K|V fp32 (phi applied to Q,K)
__device__ __half g_attnh[(size_t)MROWS * DIM];   // attention out (half) for Wo GEMM
__device__ __half g_xh[(size_t)MROWS * DIM];      // x in half
__device__ __half g_wh[4 * (size_t)DIM * DIM];    // Wq|Wk|Wv|Wo in half
__device__ float  g_kv[64 * 64 * 64];
__device__ float  g_z[64 * 64];

// ---------------- PTX helpers ------------------------------------------------
__device__ __forceinline__ uint32_t smem_u32(const void* p) {
    return (uint32_t)__cvta_generic_to_shared(p);
}

#define CP_ASYNC16(dst, src) \
    asm volatile("cp.async.cg.shared.global [%0], [%1], 16;" :: "r"(dst), "l"(src))
#define CP_COMMIT() asm volatile("cp.async.commit_group;" ::: "memory")
#define CP_WAIT_1() asm volatile("cp.async.wait_group 1;" ::: "memory")
#define CP_WAIT_0() asm volatile("cp.async.wait_group 0;" ::: "memory")

#define LDSM4(r0, r1, r2, r3, addr) \
    asm volatile("ldmatrix.sync.aligned.m8n8.x4.shared.b16 {%0,%1,%2,%3}, [%4];" \
                 : "=r"(r0), "=r"(r1), "=r"(r2), "=r"(r3) : "r"(addr))

#define MMA16816(d, a, b) \
    asm volatile("mma.sync.aligned.m16n8k16.row.col.f32.f16.f16.f32 " \
                 "{%0,%1,%2,%3}, {%4,%5,%6,%7}, {%8,%9}, {%0,%1,%2,%3};" \
                 : "+f"((d)[0]), "+f"((d)[1]), "+f"((d)[2]), "+f"((d)[3]) \
                 : "r"((a)[0]), "r"((a)[1]), "r"((a)[2]), "r"((a)[3]), \
                   "r"((b)[0]), "r"((b)[1]))

// ---------------- zero the accumulation state ------------------------------
__global__ void zero_state() {
    int i = blockIdx.x * blockDim.x + threadIdx.x;
    if (i < 64 * 64 * 64) g_kv[i] = 0.f;
    if (i < 64 * 64)      g_z[i]  = 0.f;
}

// ---------------- fp32 -> fp16 conversion ----------------------------------
__global__ void to_half4(const float* __restrict__ s, __half* __restrict__ d, int n4) {
    int i = blockIdx.x * blockDim.x + threadIdx.x;
    if (i < n4) {
        float4 v = ((const float4*)s)[i];
        __half2 h0 = __floats2half2_rn(v.x, v.y);
        __half2 h1 = __floats2half2_rn(v.z, v.w);
        ((__half2*)d)[2 * i]     = h0;
        ((__half2*)d)[2 * i + 1] = h1;
    }
}

// ---------------- stage loader (cp.async) -----------------------------------
// A: 128 rows x 32 halves (512 segs), B: 128 rows (512 segs). 4 per thread.
__device__ __forceinline__ void load_stage_h(
    uint32_t sb, int chunk,
    const __half* __restrict__ Ag, const __half* __restrict__ Wg, int tid)
{
    const int k0 = chunk * BK;
#pragma unroll
    for (int i = 0; i < 4; ++i) {
        int s = tid + i * 256;             // 0..1023
        int isB = (s >= 512) ? 1 : 0;
        int t2 = s & 511;
        int row = t2 >> 2;
        int seg = t2 & 3;
        const __half* src = (isB ? Wg : Ag) + (size_t)row * DIM + k0 + seg * 8;
        uint32_t dst = sb + (isB ? A_BYTES : 0u) + (uint32_t)row * LDHB + (uint32_t)seg * 16u;
        CP_ASYNC16(dst, src);
    }
    CP_COMMIT();
}

// ---------------- fp16 HMMA GEMM core (128x128, warp tile 64x32) ------------
__device__ __forceinline__ void gemm_h_core(
    const __half* __restrict__ Ag, const __half* __restrict__ Wg,
    const float* __restrict__ bias, float* __restrict__ Cg,
    int ldc, int isphi, __half* hsm)
{
    const int tid  = threadIdx.x;
    const int wid  = tid >> 5;
    const int lane = tid & 31;
    const int wm   = wid & 1;           // rows 64*wm
    const int wn   = wid >> 1;          // 0..3 -> cols 32*wn

    const uint32_t sbase = smem_u32(hsm);

    const int a_r = lane & 15;
    const int a_c = (lane >> 4) * 8;
    const int b_r = (lane & 7) + ((lane >> 4) & 1) * 8;
    const int b_c = ((lane >> 3) & 1) * 8;

    float acc[4][4][4];
#pragma unroll
    for (int i = 0; i < 4; ++i)
#pragma unroll
        for (int j = 0; j < 4; ++j)
#pragma unroll
            for (int e = 0; e < 4; ++e) acc[i][j][e] = 0.f;

    load_stage_h(sbase + 0u * STGB, 0, Ag, Wg, tid);
    load_stage_h(sbase + 1u * STGB, 1, Ag, Wg, tid);

    for (int c = 0; c < NCH; ++c) {
        if (c + 2 < NCH) { CP_WAIT_1(); } else { CP_WAIT_0(); }
        __syncthreads();
        if (c + 2 < NCH)
            load_stage_h(sbase + (uint32_t)((c + 2) % 3) * STGB, c + 2, Ag, Wg, tid);

        const uint32_t As = sbase + (uint32_t)(c % 3) * STGB;
        const uint32_t Bs = As + A_BYTES;

#pragma unroll
        for (int ks = 0; ks < BK; ks += 16) {
            uint32_t a[4][4];
#pragma unroll
            for (int mb = 0; mb < 4; ++mb) {
                uint32_t addr = As + (uint32_t)(wm * 64 + mb * 16 + a_r) * LDHB
                              + (uint32_t)(ks + a_c) * 2u;
                LDSM4(a[mb][0], a[mb][1], a[mb][2], a[mb][3], addr);
            }
            uint32_t b[4][2];
#pragma unroll
            for (int p = 0; p < 2; ++p) {
                uint32_t addr = Bs + (uint32_t)(wn * 32 + p * 16 + b_r) * LDHB
                              + (uint32_t)(ks + b_c) * 2u;
                uint32_t r0, r1, r2, r3;
                LDSM4(r0, r1, r2, r3, addr);
                b[2 * p][0] = r0; b[2 * p][1] = r1;
                b[2 * p + 1][0] = r2; b[2 * p + 1][1] = r3;
            }
#pragma unroll
            for (int mb = 0; mb < 4; ++mb)
#pragma unroll
                for (int nb = 0; nb < 4; ++nb)
                    MMA16816(acc[mb][nb], a[mb], b[nb]);
        }
        __syncthreads();
    }

    const int g = lane >> 2;
    const int t = lane & 3;
#pragma unroll
    for (int mb = 0; mb < 4; ++mb) {
#pragma unroll
        for (int nb = 0; nb < 4; ++nb) {
            int col  = wn * 32 + nb * 8 + 2 * t;
            float b0 = bias[col];
            float b1 = bias[col + 1];
            int row0 = wm * 64 + mb * 16 + g;
            float v0 = acc[mb][nb][0] + b0;
            float v1 = acc[mb][nb][1] + b1;
            float v2 = acc[mb][nb][2] + b0;
            float v3 = acc[mb][nb][3] + b1;
            if (isphi) {
                v0 = (v0 > 0.f) ? (v0 + 1.f) : __expf(v0);
                v1 = (v1 > 0.f) ? (v1 + 1.f) : __expf(v1);
                v2 = (v2 > 0.f) ? (v2 + 1.f) : __expf(v2);
                v3 = (v3 > 0.f) ? (v3 + 1.f) : __expf(v3);
            }
            *(float2*)(Cg + (size_t)row0 * ldc + col)       = make_float2(v0, v1);
            *(float2*)(Cg + (size_t)(row0 + 8) * ldc + col) = make_float2(v2, v3);
        }
    }
}

// ---------------- GEMM entry points -----------------------------------------
__global__ __launch_bounds__(256, 2) void qkv_gemm_h(
    const float* __restrict__ bq, const float* __restrict__ bk,
    const float* __restrict__ bv)
{
    extern __shared__ __align__(16) __half hsm[];
    const int bn = blockIdx.x * BN;    // 128 | 1024: no Q/K/V straddle
    const int bm = blockIdx.y * BM;
    const int sel   = bn >> 10;        // 0=Q 1=K 2=V
    const int wbase = bn & 1023;
    const float* bias = (sel == 0) ? bq : ((sel == 1) ? bk : bv);

    gemm_h_core(g_xh + (size_t)bm * DIM,
                g_wh + (size_t)sel * DIM * DIM + (size_t)wbase * DIM,
                bias + wbase,
                g_qkv + (size_t)bm * QKVLD + bn,
                QKVLD, (sel < 2) ? 1 : 0, hsm);
}

__global__ __launch_bounds__(256, 2) void out_gemm_h(
    const float* __restrict__ bo, float* __restrict__ out)
{
    extern __shared__ __align__(16) __half hsm[];
    const int bn = blockIdx.x * BN;
    const int bm = blockIdx.y * BM;

    gemm_h_core(g_attnh + (size_t)bm * DIM,
                g_wh + 3 * (size_t)DIM * DIM + (size_t)bn * DIM,
                bo + bn,
                out + (size_t)bm * DIM + bn,
                DIM, 0, hsm);
}

// ---------------- KV state + Z reduction (unchanged, fp32) ------------------
__global__ __launch_bounds__(256) void kv_state() {
    __shared__ float Ks[32][64];
    __shared__ float Vs[32][64];

    const int bh = blockIdx.x;
    const int b  = bh >> 4;
    const int h  = bh & 15;
    const int n0 = blockIdx.y * (SEQ / 8);

    const int tid = threadIdx.x;
    const int tx  = tid & 15;
    const int ty  = tid >> 4;
    const int lrr = tid >> 3;
    const int lcc = (tid & 7) * 8;

    float acc[4][4];
#pragma unroll
    for (int i = 0; i < 4; ++i) {
#pragma unroll
        for (int j = 0; j < 4; ++j) acc[i][j] = 0.f;
    }
    float zacc = 0.f;

    const float* Kbase = g_qkv + (size_t)(b * SEQ) * QKVLD + 1024 + h * HDIM;
    const float* Vbase = g_qkv + (size_t)(b * SEQ) * QKVLD + 2048 + h * HDIM;

    for (int n = n0; n < n0 + SEQ / 8; n += 32) {
        const float* kp = Kbase + (size_t)(n + lrr) * QKVLD + lcc;
        const float* vp = Vbase + (size_t)(n + lrr) * QKVLD + lcc;
        *(float4*)&Ks[lrr][lcc]     = *(const float4*)kp;
        *(float4*)&Ks[lrr][lcc + 4] = *(const float4*)(kp + 4);
        *(float4*)&Vs[lrr][lcc]     = *(const float4*)vp;
        *(float4*)&Vs[lrr][lcc + 4] = *(const float4*)(vp + 4);
        __syncthreads();
#pragma unroll
        for (int kk = 0; kk < 32; ++kk) {
            float rk[4];
            float rv[4];
#pragma unroll
            for (int i = 0; i < 4; ++i) rk[i] = Ks[kk][ty + 16 * i];
#pragma unroll
            for (int j = 0; j < 4; ++j) rv[j] = Vs[kk][tx + 16 * j];
#pragma unroll
            for (int i = 0; i < 4; ++i) {
#pragma unroll
                for (int j = 0; j < 4; ++j) acc[i][j] += rk[i] * rv[j];
            }
        }
        if (tid < 64) {
#pragma unroll
            for (int kk = 0; kk < 32; ++kk) zacc += Ks[kk][tid];
        }
        __syncthreads();
    }

    float* kvp = g_kv + (size_t)bh * 4096;
#pragma unroll
    for (int i = 0; i < 4; ++i) {
#pragma unroll
        for (int j = 0; j < 4; ++j) {
            atomicAdd(&kvp[(ty + 16 * i) * 64 + (tx + 16 * j)], acc[i][j]);
        }
    }
    if (tid < 64) atomicAdd(&g_z[bh * 64 + tid], zacc);
}

// ---------------- attention epilogue: HMMA with hi/lo KV + Z column ---------
// out[n,e] = (Q[n,:]·KV[:,e]) / (Q[n,:]·Z + eps); KV split into fp16 hi+lo so
// fp32 KV precision is preserved; Z rides as e-column 64 of the B matrix.
__global__ __launch_bounds__(256) void attn_epilogue_h() {
    __shared__ __half sQ[64 * 72];        // [n][d], pitch 72 halves
    __shared__ __half sKVh[96 * 72];      // [e_ext][d] transposed KV hi
    __shared__ __half sKVl[96 * 72];      // lo
    __shared__ float  sNrm[64];

    const int bh = blockIdx.x;
    const int b  = bh >> 4;
    const int h  = bh & 15;
    const int n0 = blockIdx.y * 64;
    const int tid  = threadIdx.x;
    const int wid  = tid >> 5;
    const int lane = tid & 31;

    // stage Q (fp32 -> half)
    const float* Qb = g_qkv + (size_t)(b * SEQ + n0) * QKVLD + h * HDIM;
#pragma unroll
    for (int i = 0; i < 4; ++i) {
        int idx = tid + i * 256;          // 1024 float4 units
        int r  = idx >> 4;
        int c4 = (idx & 15) << 2;
        float4 q = *(const float4*)(Qb + (size_t)r * QKVLD + c4);
        *(__half2*)&sQ[r * 72 + c4]     = __floats2half2_rn(q.x, q.y);
        *(__half2*)&sQ[r * 72 + c4 + 2] = __floats2half2_rn(q.z, q.w);
    }
    // stage KV transposed, hi/lo split
    const float* KVb = g_kv + (size_t)bh * 4096;
#pragma unroll
    for (int i = 0; i < 16; ++i) {
        int idx = tid + i * 256;          // 0..4095, = d*64 + e
        int d = idx >> 6;
        int e = idx & 63;
        float v = KVb[idx];
        __half hi = __float2half_rn(v);
        sKVh[e * 72 + d] = hi;
        sKVl[e * 72 + d] = __float2half_rn(v - __half2float(hi));
    }
    if (tid < 64) {
        float z = g_z[bh * 64 + tid];
        __half hi = __float2half_rn(z);
        sKVh[64 * 72 + tid] = hi;                              // Z at e-row 64
        sKVl[64 * 72 + tid] = __float2half_rn(z - __half2float(hi));
    }
    // rows 65..95 are junk; they only feed output columns >64 which are unused.
    __syncthreads();

    const int wm = wid & 3;               // m-tile (16 rows each)
    const int wn = wid >> 2;              // n range 40*wn
    const int a_r = lane & 15;
    const int a_c = (lane >> 4) * 8;
    const int b_r = (lane & 7) + ((lane >> 4) & 1) * 8;
    const int b_c = ((lane >> 3) & 1) * 8;

    float acc[5][4];
#pragma unroll
    for (int i = 0; i < 5; ++i)
#pragma unroll
        for (int e = 0; e < 4; ++e) acc[i][e] = 0.f;

    const uint32_t sq = smem_u32(sQ);
    const uint32_t kh = smem_u32(sKVh);
    const uint32_t kl = smem_u32(sKVl);

#pragma unroll
    for (int kt = 0; kt < 4; ++kt) {
        int k0 = kt * 16;
        uint32_t a[4];
        LDSM4(a[0], a[1], a[2], a[3],
              sq + (uint32_t)((wm * 16 + a_r) * 72 + k0 + a_c) * 2u);
#pragma unroll
        for (int pp = 0; pp < 3; ++pp) {
            int nb = wn * 40 + pp * 16;
            uint32_t addr = (uint32_t)((nb + b_r) * 72 + k0 + b_c) * 2u;
            uint32_t r0, r1, r2, r3;
            LDSM4(r0, r1, r2, r3, kh + addr);
            uint32_t s0, s1, s2, s3;
            LDSM4(s0, s1, s2, s3, kl + addr);
            uint32_t bh0[2] = {r0, r1};
            uint32_t bl0[2] = {s0, s1};
            MMA16816(acc[pp * 2], a, bh0);
            MMA16816(acc[pp * 2], a, bl0);
            if (pp * 2 + 1 < 5) {
                uint32_t bh1[2] = {r2, r3};
                uint32_t bl1[2] = {s2, s3};
                MMA16816(acc[pp * 2 + 1], a, bh1);
                MMA16816(acc[pp * 2 + 1], a, bl1);
            }
        }
    }

    const int g = lane >> 2;
    const int t = lane & 3;
    // nrm lives at ext-col 64 = wn1 local tile 3 (cols 64-71), col offset 0
    if (wn == 1 && t == 0) {
        sNrm[wm * 16 + g]     = acc[3][0];
        sNrm[wm * 16 + g + 8] = acc[3][2];
    }
    __syncthreads();

    int r0 = wm * 16 + g;
    int r1 = r0 + 8;
    float inv0 = 1.f / (sNrm[r0] + EPSV);
    float inv1 = 1.f / (sNrm[r1] + EPSV);
    __half* o0 = g_attnh + (size_t)(b * SEQ + n0 + r0) * DIM + h * HDIM;
    __half* o1 = g_attnh + (size_t)(b * SEQ + n0 + r1) * DIM + h * HDIM;
#pragma unroll
    for (int lt = 0; lt < 5; ++lt) {
        int ncol = wn * 40 + lt * 8 + 2 * t;
        if (ncol < 64) {
            *(__half2*)(o0 + ncol) = __floats2half2_rn(acc[lt][0] * inv0, acc[lt][1] * inv0);
            *(__half2*)(o1 + ncol) = __floats2half2_rn(acc[lt][2] * inv1, acc[lt][3] * inv1);
        }
    }
}

// ---------------- launch ----------------------------------------------------
extern "C" void kernel_launch(void* const* d_in, const int* in_sizes, int n_in,
                              void* d_out, int out_size) {
    const float* x  = (const float*)d_in[0];
    const float* Wq = (const float*)d_in[1];
    const float* bq = (const float*)d_in[2];
    const float* Wk = (const float*)d_in[3];
    const float* bk = (const float*)d_in[4];
    const float* Wv = (const float*)d_in[5];
    const float* bv = (const float*)d_in[6];
    const float* Wo = (const float*)d_in[7];
    const float* bo = (const float*)d_in[8];
    float* out = (float*)d_out;

    cudaFuncSetAttribute(qkv_gemm_h, cudaFuncAttributeMaxDynamicSharedMemorySize, GEMM_SMEM);
    cudaFuncSetAttribute(out_gemm_h, cudaFuncAttributeMaxDynamicSharedMemorySize, GEMM_SMEM);

    __half* gxh = 0;
    __half* gwh = 0;
    cudaGetSymbolAddress((void**)&gxh, g_xh);
    cudaGetSymbolAddress((void**)&gwh, g_wh);

    // order chosen so ncu (-s 5 -c 1) profiles qkv_gemm_h (6th launch)
    to_half4<<<(MROWS * DIM / 4 + 255) / 256, 256>>>(x, gxh, MROWS * DIM / 4);
    to_half4<<<(DIM * DIM / 4 + 255) / 256, 256>>>(Wq, gwh + 0 * (size_t)DIM * DIM, DIM * DIM / 4);
    to_half4<<<(DIM * DIM / 4 + 255) / 256, 256>>>(Wk, gwh + 1 * (size_t)DIM * DIM, DIM * DIM / 4);
    to_half4<<<(DIM * DIM / 4 + 255) / 256, 256>>>(Wv, gwh + 2 * (size_t)DIM * DIM, DIM * DIM / 4);
    to_half4<<<(DIM * DIM / 4 + 255) / 256, 256>>>(Wo, gwh + 3 * (size_t)DIM * DIM, DIM * DIM / 4);

    qkv_gemm_h<<<dim3(QKVLD / BN, MROWS / BM), 256, GEMM_SMEM>>>(bq, bk, bv);
    zero_state<<<1024, 256>>>();
    kv_state<<<dim3(64, 8), 256>>>();
    attn_epilogue_h<<<dim3(64, 64), 256>>>();
    out_gemm_h<<<dim3(DIM / BN, MROWS / BM), 256, GEMM_SMEM>>>(bo, out);
}

// round 11
// speedup vs baseline: 5.9132x; 1.0953x over previous
#include <cuda_runtime.h>
#include <cuda_fp16.h>
#include <cstdint>

#define BSZ   4
#define SEQ   4096
#define DIM   1024
#define NHEAD 16
#define HDIM  64
#define MROWS (BSZ * SEQ)
#define QKVLD 3072
#define EPSV  1e-6f

// ---- fp16 HMMA GEMM tiling: 128x128 CTA tile, BK=64, 3 stages, 2 CTAs/SM ---
#define BM 128
#define BN 128
#define BK 64                       // halves per k-chunk
#define NCH (DIM / BK)              // 16 chunks
#define LDHB 144u                   // smem row pitch bytes (72 halves)
#define A_BYTES 18432u              // 128 rows * 144B
#define STGB 36864u                 // A + B per stage
#define GEMM_SMEM (3 * STGB)        // 110592B

#define XN4 (MROWS * DIM / 4)       // 4194304
#define WN4 (DIM * DIM / 4)         // 262144

// ---------------- scratch (static device globals) ---------------------------
__device__ float  g_qkv[(size_t)MROWS * QKVLD];   // Q|K|V fp32 (phi applied to Q,K)
__device__ __half g_attnh[(size_t)MROWS * DIM];   // attention out (half) for Wo GEMM
__device__ __half g_xh[(size_t)MROWS * DIM];      // x in half
__device__ __half g_wh[4 * (size_t)DIM * DIM];    // Wq|Wk|Wv|Wo in half
__device__ float  g_kv[64 * 64 * 64];
__device__ float  g_z[64 * 64];

// ---------------- PTX helpers ------------------------------------------------
__device__ __forceinline__ uint32_t smem_u32(const void* p) {
    return (uint32_t)__cvta_generic_to_shared(p);
}

#define CP_ASYNC16(dst, src) \
    asm volatile("cp.async.cg.shared.global [%0], [%1], 16;" :: "r"(dst), "l"(src))
#define CP_COMMIT() asm volatile("cp.async.commit_group;" ::: "memory")
#define CP_WAIT_1() asm volatile("cp.async.wait_group 1;" ::: "memory")
#define CP_WAIT_0() asm volatile("cp.async.wait_group 0;" ::: "memory")

#define LDSM4(r0, r1, r2, r3, addr) \
    asm volatile("ldmatrix.sync.aligned.m8n8.x4.shared.b16 {%0,%1,%2,%3}, [%4];" \
                 : "=r"(r0), "=r"(r1), "=r"(r2), "=r"(r3) : "r"(addr))

#define MMA16816(d, a, b) \
    asm volatile("mma.sync.aligned.m16n8k16.row.col.f32.f16.f16.f32 " \
                 "{%0,%1,%2,%3}, {%4,%5,%6,%7}, {%8,%9}, {%0,%1,%2,%3};" \
                 : "+f"((d)[0]), "+f"((d)[1]), "+f"((d)[2]), "+f"((d)[3]) \
                 : "r"((a)[0]), "r"((a)[1]), "r"((a)[2]), "r"((a)[3]), \
                   "r"((b)[0]), "r"((b)[1]))

// ---------------- zero the accumulation state ------------------------------
__global__ void zero_state() {
    int i = blockIdx.x * blockDim.x + threadIdx.x;
    if (i < 64 * 64 * 64) g_kv[i] = 0.f;
    if (i < 64 * 64)      g_z[i]  = 0.f;
}

// ---------------- fused fp32 -> fp16 conversion (x + 4 weights) -------------
__global__ void conv_all(const float* __restrict__ x,
                         const float* __restrict__ Wq, const float* __restrict__ Wk,
                         const float* __restrict__ Wv, const float* __restrict__ Wo)
{
    int i = blockIdx.x * blockDim.x + threadIdx.x;
    if (i >= XN4 + 4 * WN4) return;
    const float* s;
    __half* d;
    int j;
    if (i < XN4) {
        s = x; d = g_xh; j = i;
    } else {
        int t = i - XN4;
        int w = t >> 18;              // / WN4 (262144 = 2^18)
        j = t & (WN4 - 1);
        s = (w == 0) ? Wq : ((w == 1) ? Wk : ((w == 2) ? Wv : Wo));
        d = g_wh + (size_t)w * DIM * DIM;
    }
    float4 v = ((const float4*)s)[j];
    ((__half2*)d)[2 * j]     = __floats2half2_rn(v.x, v.y);
    ((__half2*)d)[2 * j + 1] = __floats2half2_rn(v.z, v.w);
}

// ---------------- stage loader (cp.async, BK=64) ----------------------------
// A: 128 rows x 64 halves (1024 segs), B: 128 rows (1024 segs). 8 per thread.
__device__ __forceinline__ void load_stage_h(
    uint32_t sb, int chunk,
    const __half* __restrict__ Ag, const __half* __restrict__ Wg, int tid)
{
    const int k0 = chunk * BK;
#pragma unroll
    for (int i = 0; i < 8; ++i) {
        int s = tid + i * 256;             // 0..2047
        int isB = (s >= 1024) ? 1 : 0;
        int t2 = s & 1023;
        int row = t2 >> 3;
        int seg = t2 & 7;
        const __half* src = (isB ? Wg : Ag) + (size_t)row * DIM + k0 + seg * 8;
        uint32_t dst = sb + (isB ? A_BYTES : 0u) + (uint32_t)row * LDHB + (uint32_t)seg * 16u;
        CP_ASYNC16(dst, src);
    }
    CP_COMMIT();
}

// ---------------- fp16 HMMA GEMM core (128x128, warp tile 64x32) ------------
__device__ __forceinline__ void gemm_h_core(
    const __half* __restrict__ Ag, const __half* __restrict__ Wg,
    const float* __restrict__ bias, float* __restrict__ Cg,
    int ldc, int isphi, __half* hsm)
{
    const int tid  = threadIdx.x;
    const int wid  = tid >> 5;
    const int lane = tid & 31;
    const int wm   = wid & 1;           // rows 64*wm
    const int wn   = wid >> 1;          // 0..3 -> cols 32*wn

    const uint32_t sbase = smem_u32(hsm);

    const int a_r = lane & 15;
    const int a_c = (lane >> 4) * 8;
    const int b_r = (lane & 7) + ((lane >> 4) & 1) * 8;
    const int b_c = ((lane >> 3) & 1) * 8;

    float acc[4][4][4];
#pragma unroll
    for (int i = 0; i < 4; ++i)
#pragma unroll
        for (int j = 0; j < 4; ++j)
#pragma unroll
            for (int e = 0; e < 4; ++e) acc[i][j][e] = 0.f;

    load_stage_h(sbase + 0u * STGB, 0, Ag, Wg, tid);
    load_stage_h(sbase + 1u * STGB, 1, Ag, Wg, tid);

    for (int c = 0; c < NCH; ++c) {
        if (c + 2 < NCH) { CP_WAIT_1(); } else { CP_WAIT_0(); }
        __syncthreads();
        if (c + 2 < NCH)
            load_stage_h(sbase + (uint32_t)((c + 2) % 3) * STGB, c + 2, Ag, Wg, tid);

        const uint32_t As = sbase + (uint32_t)(c % 3) * STGB;
        const uint32_t Bs = As + A_BYTES;

#pragma unroll
        for (int ks = 0; ks < BK; ks += 16) {
            uint32_t a[4][4];
#pragma unroll
            for (int mb = 0; mb < 4; ++mb) {
                uint32_t addr = As + (uint32_t)(wm * 64 + mb * 16 + a_r) * LDHB
                              + (uint32_t)(ks + a_c) * 2u;
                LDSM4(a[mb][0], a[mb][1], a[mb][2], a[mb][3], addr);
            }
            uint32_t b[4][2];
#pragma unroll
            for (int p = 0; p < 2; ++p) {
                uint32_t addr = Bs + (uint32_t)(wn * 32 + p * 16 + b_r) * LDHB
                              + (uint32_t)(ks + b_c) * 2u;
                uint32_t r0, r1, r2, r3;
                LDSM4(r0, r1, r2, r3, addr);
                b[2 * p][0] = r0; b[2 * p][1] = r1;
                b[2 * p + 1][0] = r2; b[2 * p + 1][1] = r3;
            }
#pragma unroll
            for (int mb = 0; mb < 4; ++mb)
#pragma unroll
                for (int nb = 0; nb < 4; ++nb)
                    MMA16816(acc[mb][nb], a[mb], b[nb]);
        }
        __syncthreads();
    }

    const int g = lane >> 2;
    const int t = lane & 3;
#pragma unroll
    for (int mb = 0; mb < 4; ++mb) {
#pragma unroll
        for (int nb = 0; nb < 4; ++nb) {
            int col  = wn * 32 + nb * 8 + 2 * t;
            float b0 = bias[col];
            float b1 = bias[col + 1];
            int row0 = wm * 64 + mb * 16 + g;
            float v0 = acc[mb][nb][0] + b0;
            float v1 = acc[mb][nb][1] + b1;
            float v2 = acc[mb][nb][2] + b0;
            float v3 = acc[mb][nb][3] + b1;
            if (isphi) {
                v0 = (v0 > 0.f) ? (v0 + 1.f) : __expf(v0);
                v1 = (v1 > 0.f) ? (v1 + 1.f) : __expf(v1);
                v2 = (v2 > 0.f) ? (v2 + 1.f) : __expf(v2);
                v3 = (v3 > 0.f) ? (v3 + 1.f) : __expf(v3);
            }
            *(float2*)(Cg + (size_t)row0 * ldc + col)       = make_float2(v0, v1);
            *(float2*)(Cg + (size_t)(row0 + 8) * ldc + col) = make_float2(v2, v3);
        }
    }
}

// ---------------- GEMM entry points -----------------------------------------
__global__ __launch_bounds__(256, 2) void qkv_gemm_h(
    const float* __restrict__ bq, const float* __restrict__ bk,
    const float* __restrict__ bv)
{
    extern __shared__ __align__(16) __half hsm[];
    const int bn = blockIdx.x * BN;    // 128 | 1024: no Q/K/V straddle
    const int bm = blockIdx.y * BM;
    const int sel   = bn >> 10;        // 0=Q 1=K 2=V
    const int wbase = bn & 1023;
    const float* bias = (sel == 0) ? bq : ((sel == 1) ? bk : bv);

    gemm_h_core(g_xh + (size_t)bm * DIM,
                g_wh + (size_t)sel * DIM * DIM + (size_t)wbase * DIM,
                bias + wbase,
                g_qkv + (size_t)bm * QKVLD + bn,
                QKVLD, (sel < 2) ? 1 : 0, hsm);
}

__global__ __launch_bounds__(256, 2) void out_gemm_h(
    const float* __restrict__ bo, float* __restrict__ out)
{
    extern __shared__ __align__(16) __half hsm[];
    const int bn = blockIdx.x * BN;
    const int bm = blockIdx.y * BM;

    gemm_h_core(g_attnh + (size_t)bm * DIM,
                g_wh + 3 * (size_t)DIM * DIM + (size_t)bn * DIM,
                bo + bn,
                out + (size_t)bm * DIM + bn,
                DIM, 0, hsm);
}

// ---------------- KV state + Z reduction (fp32) -----------------------------
__global__ __launch_bounds__(256) void kv_state() {
    __shared__ float Ks[32][64];
    __shared__ float Vs[32][64];

    const int bh = blockIdx.x;
    const int b  = bh >> 4;
    const int h  = bh & 15;
    const int n0 = blockIdx.y * (SEQ / 8);

    const int tid = threadIdx.x;
    const int tx  = tid & 15;
    const int ty  = tid >> 4;
    const int lrr = tid >> 3;
    const int lcc = (tid & 7) * 8;

    float acc[4][4];
#pragma unroll
    for (int i = 0; i < 4; ++i) {
#pragma unroll
        for (int j = 0; j < 4; ++j) acc[i][j] = 0.f;
    }
    float zacc = 0.f;

    const float* Kbase = g_qkv + (size_t)(b * SEQ) * QKVLD + 1024 + h * HDIM;
    const float* Vbase = g_qkv + (size_t)(b * SEQ) * QKVLD + 2048 + h * HDIM;

    for (int n = n0; n < n0 + SEQ / 8; n += 32) {
        const float* kp = Kbase + (size_t)(n + lrr) * QKVLD + lcc;
        const float* vp = Vbase + (size_t)(n + lrr) * QKVLD + lcc;
        *(float4*)&Ks[lrr][lcc]     = *(const float4*)kp;
        *(float4*)&Ks[lrr][lcc + 4] = *(const float4*)(kp + 4);
        *(float4*)&Vs[lrr][lcc]     = *(const float4*)vp;
        *(float4*)&Vs[lrr][lcc + 4] = *(const float4*)(vp + 4);
        __syncthreads();
#pragma unroll
        for (int kk = 0; kk < 32; ++kk) {
            float rk[4];
            float rv[4];
#pragma unroll
            for (int i = 0; i < 4; ++i) rk[i] = Ks[kk][ty + 16 * i];
#pragma unroll
            for (int j = 0; j < 4; ++j) rv[j] = Vs[kk][tx + 16 * j];
#pragma unroll
            for (int i = 0; i < 4; ++i) {
#pragma unroll
                for (int j = 0; j < 4; ++j) acc[i][j] += rk[i] * rv[j];
            }
        }
        if (tid < 64) {
#pragma unroll
            for (int kk = 0; kk < 32; ++kk) zacc += Ks[kk][tid];
        }
        __syncthreads();
    }

    float* kvp = g_kv + (size_t)bh * 4096;
#pragma unroll
    for (int i = 0; i < 4; ++i) {
#pragma unroll
        for (int j = 0; j < 4; ++j) {
            atomicAdd(&kvp[(ty + 16 * i) * 64 + (tx + 16 * j)], acc[i][j]);
        }
    }
    if (tid < 64) atomicAdd(&g_z[bh * 64 + tid], zacc);
}

// ---------------- attention epilogue: HMMA with hi/lo KV + Z column ---------
__global__ __launch_bounds__(256) void attn_epilogue_h() {
    __shared__ __half sQ[64 * 72];        // [n][d], pitch 72 halves
    __shared__ __half sKVh[96 * 72];      // [e_ext][d] transposed KV hi
    __shared__ __half sKVl[96 * 72];      // lo
    __shared__ float  sNrm[64];

    const int bh = blockIdx.x;
    const int b  = bh >> 4;
    const int h  = bh & 15;
    const int n0 = blockIdx.y * 64;
    const int tid  = threadIdx.x;
    const int wid  = tid >> 5;
    const int lane = tid & 31;

    const float* Qb = g_qkv + (size_t)(b * SEQ + n0) * QKVLD + h * HDIM;
#pragma unroll
    for (int i = 0; i < 4; ++i) {
        int idx = tid + i * 256;
        int r  = idx >> 4;
        int c4 = (idx & 15) << 2;
        float4 q = *(const float4*)(Qb + (size_t)r * QKVLD + c4);
        *(__half2*)&sQ[r * 72 + c4]     = __floats2half2_rn(q.x, q.y);
        *(__half2*)&sQ[r * 72 + c4 + 2] = __floats2half2_rn(q.z, q.w);
    }
    const float* KVb = g_kv + (size_t)bh * 4096;
#pragma unroll
    for (int i = 0; i < 16; ++i) {
        int idx = tid + i * 256;
        int d = idx >> 6;
        int e = idx & 63;
        float v = KVb[idx];
        __half hi = __float2half_rn(v);
        sKVh[e * 72 + d] = hi;
        sKVl[e * 72 + d] = __float2half_rn(v - __half2float(hi));
    }
    if (tid < 64) {
        float z = g_z[bh * 64 + tid];
        __half hi = __float2half_rn(z);
        sKVh[64 * 72 + tid] = hi;
        sKVl[64 * 72 + tid] = __float2half_rn(z - __half2float(hi));
    }
    __syncthreads();

    const int wm = wid & 3;
    const int wn = wid >> 2;
    const int a_r = lane & 15;
    const int a_c = (lane >> 4) * 8;
    const int b_r = (lane & 7) + ((lane >> 4) & 1) * 8;
    const int b_c = ((lane >> 3) & 1) * 8;

    float acc[5][4];
#pragma unroll
    for (int i = 0; i < 5; ++i)
#pragma unroll
        for (int e = 0; e < 4; ++e) acc[i][e] = 0.f;

    const uint32_t sq = smem_u32(sQ);
    const uint32_t kh = smem_u32(sKVh);
    const uint32_t kl = smem_u32(sKVl);

#pragma unroll
    for (int kt = 0; kt < 4; ++kt) {
        int k0 = kt * 16;
        uint32_t a[4];
        LDSM4(a[0], a[1], a[2], a[3],
              sq + (uint32_t)((wm * 16 + a_r) * 72 + k0 + a_c) * 2u);
#pragma unroll
        for (int pp = 0; pp < 3; ++pp) {
            int nb = wn * 40 + pp * 16;
            uint32_t addr = (uint32_t)((nb + b_r) * 72 + k0 + b_c) * 2u;
            uint32_t r0, r1, r2, r3;
            LDSM4(r0, r1, r2, r3, kh + addr);
            uint32_t s0, s1, s2, s3;
            LDSM4(s0, s1, s2, s3, kl + addr);
            uint32_t bh0[2] = {r0, r1};
            uint32_t bl0[2] = {s0, s1};
            MMA16816(acc[pp * 2], a, bh0);
            MMA16816(acc[pp * 2], a, bl0);
            if (pp * 2 + 1 < 5) {
                uint32_t bh1[2] = {r2, r3};
                uint32_t bl1[2] = {s2, s3};
                MMA16816(acc[pp * 2 + 1], a, bh1);
                MMA16816(acc[pp * 2 + 1], a, bl1);
            }
        }
    }

    const int g = lane >> 2;
    const int t = lane & 3;
    if (wn == 1 && t == 0) {
        sNrm[wm * 16 + g]     = acc[3][0];
        sNrm[wm * 16 + g + 8] = acc[3][2];
    }
    __syncthreads();

    int r0 = wm * 16 + g;
    int r1 = r0 + 8;
    float inv0 = 1.f / (sNrm[r0] + EPSV);
    float inv1 = 1.f / (sNrm[r1] + EPSV);
    __half* o0 = g_attnh + (size_t)(b * SEQ + n0 + r0) * DIM + h * HDIM;
    __half* o1 = g_attnh + (size_t)(b * SEQ + n0 + r1) * DIM + h * HDIM;
#pragma unroll
    for (int lt = 0; lt < 5; ++lt) {
        int ncol = wn * 40 + lt * 8 + 2 * t;
        if (ncol < 64) {
            *(__half2*)(o0 + ncol) = __floats2half2_rn(acc[lt][0] * inv0, acc[lt][1] * inv0);
            *(__half2*)(o1 + ncol) = __floats2half2_rn(acc[lt][2] * inv1, acc[lt][3] * inv1);
        }
    }
}

// ---------------- launch ----------------------------------------------------
extern "C" void kernel_launch(void* const* d_in, const int* in_sizes, int n_in,
                              void* d_out, int out_size) {
    const float* x  = (const float*)d_in[0];
    const float* Wq = (const float*)d_in[1];
    const float* bq = (const float*)d_in[2];
    const float* Wk = (const float*)d_in[3];
    const float* bk = (const float*)d_in[4];
    const float* Wv = (const float*)d_in[5];
    const float* bv = (const float*)d_in[6];
    const float* Wo = (const float*)d_in[7];
    const float* bo = (const float*)d_in[8];
    float* out = (float*)d_out;

    cudaFuncSetAttribute(qkv_gemm_h, cudaFuncAttributeMaxDynamicSharedMemorySize, GEMM_SMEM);
    cudaFuncSetAttribute(out_gemm_h, cudaFuncAttributeMaxDynamicSharedMemorySize, GEMM_SMEM);

    // launch order: 6th launch (ncu -s 5 -c 1 target) = out_gemm_h
    conv_all<<<(XN4 + 4 * WN4 + 255) / 256, 256>>>(x, Wq, Wk, Wv, Wo);
    qkv_gemm_h<<<dim3(QKVLD / BN, MROWS / BM), 256, GEMM_SMEM>>>(bq, bk, bv);
    zero_state<<<1024, 256>>>();
    kv_state<<<dim3(64, 8), 256>>>();
    attn_epilogue_h<<<dim3(64, 64), 256>>>();
    out_gemm_h<<<dim3(DIM / BN, MROWS / BM), 256, GEMM_SMEM>>>(bo, out);
}

// round 12
// speedup vs baseline: 6.8743x; 1.1625x over previous
#include <cuda_runtime.h>
#include <cuda_fp16.h>
#include <cstdint>

#define BSZ   4
#define SEQ   4096
#define DIM   1024
#define NHEAD 16
#define HDIM  64
#define MROWS (BSZ * SEQ)
#define QKVLD 3072
#define EPSV  1e-6f

// ---- fp16 HMMA GEMM tiling: 128x128 CTA tile, BK=64, 3 stages, 2 CTAs/SM ---
#define BM 128
#define BN 128
#define BK 64
#define NCH (DIM / BK)              // 16 chunks
#define LDHB 144u                   // smem row pitch bytes (72 halves)
#define A_BYTES 18432u
#define STGB 36864u
#define GEMM_SMEM (3 * STGB)        // 110592B

#define XN4 (MROWS * DIM / 4)
#define WN4 (DIM * DIM / 4)

// ---------------- scratch (static device globals) ---------------------------
__device__ __half g_qkvh[(size_t)MROWS * QKVLD];  // Q|K|V half (phi applied to Q,K)
__device__ __half g_attnh[(size_t)MROWS * DIM];   // attention out (half)
__device__ __half g_xh[(size_t)MROWS * DIM];      // x in half
__device__ __half g_wh[4 * (size_t)DIM * DIM];    // Wq|Wk|Wv|Wo in half
__device__ float  g_kv[64 * 64 * 64];
__device__ float  g_z[64 * 64];

// ---------------- PTX helpers ------------------------------------------------
__device__ __forceinline__ uint32_t smem_u32(const void* p) {
    return (uint32_t)__cvta_generic_to_shared(p);
}

#define CP_ASYNC16(dst, src) \
    asm volatile("cp.async.cg.shared.global [%0], [%1], 16;" :: "r"(dst), "l"(src))
#define CP_COMMIT() asm volatile("cp.async.commit_group;" ::: "memory")
#define CP_WAIT_1() asm volatile("cp.async.wait_group 1;" ::: "memory")
#define CP_WAIT_0() asm volatile("cp.async.wait_group 0;" ::: "memory")

#define LDSM4(r0, r1, r2, r3, addr) \
    asm volatile("ldmatrix.sync.aligned.m8n8.x4.shared.b16 {%0,%1,%2,%3}, [%4];" \
                 : "=r"(r0), "=r"(r1), "=r"(r2), "=r"(r3) : "r"(addr))

#define LDSM4T(r0, r1, r2, r3, addr) \
    asm volatile("ldmatrix.sync.aligned.m8n8.x4.trans.shared.b16 {%0,%1,%2,%3}, [%4];" \
                 : "=r"(r0), "=r"(r1), "=r"(r2), "=r"(r3) : "r"(addr))

#define LDSM2T(r0, r1, addr) \
    asm volatile("ldmatrix.sync.aligned.m8n8.x2.trans.shared.b16 {%0,%1}, [%2];" \
                 : "=r"(r0), "=r"(r1) : "r"(addr))

#define MMA16816(d, a, b) \
    asm volatile("mma.sync.aligned.m16n8k16.row.col.f32.f16.f16.f32 " \
                 "{%0,%1,%2,%3}, {%4,%5,%6,%7}, {%8,%9}, {%0,%1,%2,%3};" \
                 : "+f"((d)[0]), "+f"((d)[1]), "+f"((d)[2]), "+f"((d)[3]) \
                 : "r"((a)[0]), "r"((a)[1]), "r"((a)[2]), "r"((a)[3]), \
                   "r"((b)[0]), "r"((b)[1]))

// ---------------- zero the accumulation state ------------------------------
__global__ void zero_state() {
    int i = blockIdx.x * blockDim.x + threadIdx.x;
    if (i < 64 * 64 * 64) g_kv[i] = 0.f;
    if (i < 64 * 64)      g_z[i]  = 0.f;
}

// ---------------- fused fp32 -> fp16 conversion (x + 4 weights) -------------
__global__ void conv_all(const float* __restrict__ x,
                         const float* __restrict__ Wq, const float* __restrict__ Wk,
                         const float* __restrict__ Wv, const float* __restrict__ Wo)
{
    int i = blockIdx.x * blockDim.x + threadIdx.x;
    if (i >= XN4 + 4 * WN4) return;
    const float* s;
    __half* d;
    int j;
    if (i < XN4) {
        s = x; d = g_xh; j = i;
    } else {
        int t = i - XN4;
        int w = t >> 18;
        j = t & (WN4 - 1);
        s = (w == 0) ? Wq : ((w == 1) ? Wk : ((w == 2) ? Wv : Wo));
        d = g_wh + (size_t)w * DIM * DIM;
    }
    float4 v = ((const float4*)s)[j];
    ((__half2*)d)[2 * j]     = __floats2half2_rn(v.x, v.y);
    ((__half2*)d)[2 * j + 1] = __floats2half2_rn(v.z, v.w);
}

// ---------------- stage loader (cp.async, BK=64) ----------------------------
__device__ __forceinline__ void load_stage_h(
    uint32_t sb, int chunk,
    const __half* __restrict__ Ag, const __half* __restrict__ Wg, int tid)
{
    const int k0 = chunk * BK;
#pragma unroll
    for (int i = 0; i < 8; ++i) {
        int s = tid + i * 256;
        int isB = (s >= 1024) ? 1 : 0;
        int t2 = s & 1023;
        int row = t2 >> 3;
        int seg = t2 & 7;
        const __half* src = (isB ? Wg : Ag) + (size_t)row * DIM + k0 + seg * 8;
        uint32_t dst = sb + (isB ? A_BYTES : 0u) + (uint32_t)row * LDHB + (uint32_t)seg * 16u;
        CP_ASYNC16(dst, src);
    }
    CP_COMMIT();
}

// ---------------- fp16 HMMA GEMM core (128x128, warp tile 64x32) ------------
__device__ __forceinline__ void gemm_h_core(
    const __half* __restrict__ Ag, const __half* __restrict__ Wg,
    const float* __restrict__ bias, void* Cg,
    int ldc, int isphi, int outhalf, __half* hsm)
{
    const int tid  = threadIdx.x;
    const int wid  = tid >> 5;
    const int lane = tid & 31;
    const int wm   = wid & 1;
    const int wn   = wid >> 1;

    const uint32_t sbase = smem_u32(hsm);

    const int a_r = lane & 15;
    const int a_c = (lane >> 4) * 8;
    const int b_r = (lane & 7) + ((lane >> 4) & 1) * 8;
    const int b_c = ((lane >> 3) & 1) * 8;

    float acc[4][4][4];
#pragma unroll
    for (int i = 0; i < 4; ++i)
#pragma unroll
        for (int j = 0; j < 4; ++j)
#pragma unroll
            for (int e = 0; e < 4; ++e) acc[i][j][e] = 0.f;

    load_stage_h(sbase + 0u * STGB, 0, Ag, Wg, tid);
    load_stage_h(sbase + 1u * STGB, 1, Ag, Wg, tid);

    for (int c = 0; c < NCH; ++c) {
        if (c + 2 < NCH) { CP_WAIT_1(); } else { CP_WAIT_0(); }
        __syncthreads();
        if (c + 2 < NCH)
            load_stage_h(sbase + (uint32_t)((c + 2) % 3) * STGB, c + 2, Ag, Wg, tid);

        const uint32_t As = sbase + (uint32_t)(c % 3) * STGB;
        const uint32_t Bs = As + A_BYTES;

#pragma unroll
        for (int ks = 0; ks < BK; ks += 16) {
            uint32_t a[4][4];
#pragma unroll
            for (int mb = 0; mb < 4; ++mb) {
                uint32_t addr = As + (uint32_t)(wm * 64 + mb * 16 + a_r) * LDHB
                              + (uint32_t)(ks + a_c) * 2u;
                LDSM4(a[mb][0], a[mb][1], a[mb][2], a[mb][3], addr);
            }
            uint32_t b[4][2];
#pragma unroll
            for (int p = 0; p < 2; ++p) {
                uint32_t addr = Bs + (uint32_t)(wn * 32 + p * 16 + b_r) * LDHB
                              + (uint32_t)(ks + b_c) * 2u;
                uint32_t r0, r1, r2, r3;
                LDSM4(r0, r1, r2, r3, addr);
                b[2 * p][0] = r0; b[2 * p][1] = r1;
                b[2 * p + 1][0] = r2; b[2 * p + 1][1] = r3;
            }
#pragma unroll
            for (int mb = 0; mb < 4; ++mb)
#pragma unroll
                for (int nb = 0; nb < 4; ++nb)
                    MMA16816(acc[mb][nb], a[mb], b[nb]);
        }
        __syncthreads();
    }

    const int g = lane >> 2;
    const int t = lane & 3;
#pragma unroll
    for (int mb = 0; mb < 4; ++mb) {
#pragma unroll
        for (int nb = 0; nb < 4; ++nb) {
            int col  = wn * 32 + nb * 8 + 2 * t;
            float b0 = bias[col];
            float b1 = bias[col + 1];
            int row0 = wm * 64 + mb * 16 + g;
            float v0 = acc[mb][nb][0] + b0;
            float v1 = acc[mb][nb][1] + b1;
            float v2 = acc[mb][nb][2] + b0;
            float v3 = acc[mb][nb][3] + b1;
            if (isphi) {
                v0 = (v0 > 0.f) ? (v0 + 1.f) : __expf(v0);
                v1 = (v1 > 0.f) ? (v1 + 1.f) : __expf(v1);
                v2 = (v2 > 0.f) ? (v2 + 1.f) : __expf(v2);
                v3 = (v3 > 0.f) ? (v3 + 1.f) : __expf(v3);
            }
            if (outhalf) {
                __half* C = (__half*)Cg;
                *(__half2*)(C + (size_t)row0 * ldc + col)       = __floats2half2_rn(v0, v1);
                *(__half2*)(C + (size_t)(row0 + 8) * ldc + col) = __floats2half2_rn(v2, v3);
            } else {
                float* C = (float*)Cg;
                *(float2*)(C + (size_t)row0 * ldc + col)       = make_float2(v0, v1);
                *(float2*)(C + (size_t)(row0 + 8) * ldc + col) = make_float2(v2, v3);
            }
        }
    }
}

// ---------------- GEMM entry points -----------------------------------------
__global__ __launch_bounds__(256, 2) void qkv_gemm_h(
    const float* __restrict__ bq, const float* __restrict__ bk,
    const float* __restrict__ bv)
{
    extern __shared__ __align__(16) __half hsm[];
    const int bn = blockIdx.x * BN;
    const int bm = blockIdx.y * BM;
    const int sel   = bn >> 10;
    const int wbase = bn & 1023;
    const float* bias = (sel == 0) ? bq : ((sel == 1) ? bk : bv);

    gemm_h_core(g_xh + (size_t)bm * DIM,
                g_wh + (size_t)sel * DIM * DIM + (size_t)wbase * DIM,
                bias + wbase,
                g_qkvh + (size_t)bm * QKVLD + bn,
                QKVLD, (sel < 2) ? 1 : 0, 1, hsm);
}

__global__ __launch_bounds__(256, 2) void out_gemm_h(
    const float* __restrict__ bo, float* __restrict__ out)
{
    extern __shared__ __align__(16) __half hsm[];
    const int bn = blockIdx.x * BN;
    const int bm = blockIdx.y * BM;

    gemm_h_core(g_attnh + (size_t)bm * DIM,
                g_wh + 3 * (size_t)DIM * DIM + (size_t)bn * DIM,
                bo + bn,
                out + (size_t)bm * DIM + bn,
                DIM, 0, 0, hsm);
}

// ---------------- KV state + Z via HMMA -------------------------------------
// KV[d,e] = sum_n K[n,d] * V[n,e]; Z[d] = sum_n K[n,d] (ones column e=64).
// A = K^T via ldmatrix.trans; B = V^T via ldmatrix.trans. grid (64 bh, 8 splits).
__global__ __launch_bounds__(128) void kv_state_h() {
    __shared__ __half Kt[64 * 72];        // [n][d], pitch 72 halves
    __shared__ __half Vt[64 * 72 + 8];    // [n][e_ext], col 64 = 1.0, 65-71 = 0

    const int bh = blockIdx.x;
    const int b  = bh >> 4;
    const int h  = bh & 15;
    const int n0 = blockIdx.y * 512;

    const int tid  = threadIdx.x;
    const int wid  = tid >> 5;            // 0..3 -> d rows 16*wid
    const int lane = tid & 31;

    // init V ext columns once (loads never touch cols 64-71)
    for (int u = tid; u < 256; u += 128) {      // 64 rows x 4 half2
        int r  = u >> 2;
        int c2 = u & 3;
        __half2 v = (c2 == 0) ? __halves2half2(__float2half(1.f), __float2half(0.f))
                              : __halves2half2(__float2half(0.f), __float2half(0.f));
        *(__half2*)&Vt[r * 72 + 64 + c2 * 2] = v;
    }

    const __half* Kbase = g_qkvh + (size_t)(b * SEQ) * QKVLD + 1024 + h * HDIM;
    const __half* Vbase = g_qkvh + (size_t)(b * SEQ) * QKVLD + 2048 + h * HDIM;

    const uint32_t kb = smem_u32(Kt);
    const uint32_t vb = smem_u32(Vt);

    // trans-ldmatrix lane patterns
    const int tA_r = (lane & 7) + ((lane >> 4) & 1) * 8;   // k-row for A^T load
    const int tA_c = ((lane >> 3) & 1) * 8;                // d-col
    const int tB_r = (lane & 7) + ((lane >> 3) & 1) * 8;   // k-row for B^T load
    const int tB_c = ((lane >> 4) & 1) * 8;                // e-col

    float acc[9][4];
#pragma unroll
    for (int i = 0; i < 9; ++i)
#pragma unroll
        for (int e = 0; e < 4; ++e) acc[i][e] = 0.f;

    for (int t = 0; t < 8; ++t) {
        const int nb = n0 + t * 64;
        __syncthreads();                 // protect smem from previous iter's readers
#pragma unroll
        for (int i = 0; i < 8; ++i) {
            int s   = tid + i * 128;     // 0..1023
            int isV = (s >= 512) ? 1 : 0;
            int s2  = s & 511;
            int r   = s2 >> 3;
            int seg = s2 & 7;
            const __half* src = (isV ? Vbase : Kbase) + (size_t)(nb + r) * QKVLD + seg * 8;
            uint32_t dst = (isV ? vb : kb) + (uint32_t)r * 144u + (uint32_t)seg * 16u;
            CP_ASYNC16(dst, src);
        }
        CP_COMMIT();
        CP_WAIT_0();
        __syncthreads();

#pragma unroll
        for (int k0 = 0; k0 < 64; k0 += 16) {
            uint32_t a[4];
            LDSM4T(a[0], a[1], a[2], a[3],
                   kb + (uint32_t)((k0 + tA_r) * 72 + wid * 16 + tA_c) * 2u);
#pragma unroll
            for (int p = 0; p < 4; ++p) {
                uint32_t r0, r1, r2, r3;
                LDSM4T(r0, r1, r2, r3,
                       vb + (uint32_t)((k0 + tB_r) * 72 + p * 16 + tB_c) * 2u);
                uint32_t b0[2] = {r0, r1};
                uint32_t b1[2] = {r2, r3};
                MMA16816(acc[2 * p], a, b0);
                MMA16816(acc[2 * p + 1], a, b1);
            }
            {   // Z ones-column tile (e 64-71)
                uint32_t r0, r1;
                LDSM2T(r0, r1, vb + (uint32_t)((k0 + tB_r) * 72 + 64) * 2u);
                uint32_t bz[2] = {r0, r1};
                MMA16816(acc[8], a, bz);
            }
        }
    }

    // atomic reduction
    const int g = lane >> 2;
    const int t = lane & 3;
    const int d0 = wid * 16 + g;
    const int d1 = d0 + 8;
    float* kvp = g_kv + (size_t)bh * 4096;
#pragma unroll
    for (int nb = 0; nb < 8; ++nb) {
        int e0 = nb * 8 + 2 * t;
        atomicAdd(&kvp[d0 * 64 + e0],     acc[nb][0]);
        atomicAdd(&kvp[d0 * 64 + e0 + 1], acc[nb][1]);
        atomicAdd(&kvp[d1 * 64 + e0],     acc[nb][2]);
        atomicAdd(&kvp[d1 * 64 + e0 + 1], acc[nb][3]);
    }
    if (t == 0) {
        atomicAdd(&g_z[bh * 64 + d0], acc[8][0]);
        atomicAdd(&g_z[bh * 64 + d1], acc[8][2]);
    }
}

// ---------------- attention epilogue: HMMA with hi/lo KV + Z column ---------
__global__ __launch_bounds__(256) void attn_epilogue_h() {
    __shared__ __half sQ[64 * 72];
    __shared__ __half sKVh[96 * 72];
    __shared__ __half sKVl[96 * 72];
    __shared__ float  sNrm[64];

    const int bh = blockIdx.x;
    const int b  = bh >> 4;
    const int h  = bh & 15;
    const int n0 = blockIdx.y * 64;
    const int tid  = threadIdx.x;
    const int wid  = tid >> 5;
    const int lane = tid & 31;

    // stage Q (already half)
    const __half* Qb = g_qkvh + (size_t)(b * SEQ + n0) * QKVLD + h * HDIM;
#pragma unroll
    for (int i = 0; i < 2; ++i) {
        int idx = tid + i * 256;          // 512 x 16B segs
        int r   = idx >> 3;
        int seg = idx & 7;
        *(uint4*)&sQ[r * 72 + seg * 8] = *(const uint4*)(Qb + (size_t)r * QKVLD + seg * 8);
    }
    const float* KVb = g_kv + (size_t)bh * 4096;
#pragma unroll
    for (int i = 0; i < 16; ++i) {
        int idx = tid + i * 256;
        int d = idx >> 6;
        int e = idx & 63;
        float v = KVb[idx];
        __half hi = __float2half_rn(v);
        sKVh[e * 72 + d] = hi;
        sKVl[e * 72 + d] = __float2half_rn(v - __half2float(hi));
    }
    if (tid < 64) {
        float z = g_z[bh * 64 + tid];
        __half hi = __float2half_rn(z);
        sKVh[64 * 72 + tid] = hi;
        sKVl[64 * 72 + tid] = __float2half_rn(z - __half2float(hi));
    }
    __syncthreads();

    const int wm = wid & 3;
    const int wn = wid >> 2;
    const int a_r = lane & 15;
    const int a_c = (lane >> 4) * 8;
    const int b_r = (lane & 7) + ((lane >> 4) & 1) * 8;
    const int b_c = ((lane >> 3) & 1) * 8;

    float acc[5][4];
#pragma unroll
    for (int i = 0; i < 5; ++i)
#pragma unroll
        for (int e = 0; e < 4; ++e) acc[i][e] = 0.f;

    const uint32_t sq = smem_u32(sQ);
    const uint32_t kh = smem_u32(sKVh);
    const uint32_t kl = smem_u32(sKVl);

#pragma unroll
    for (int kt = 0; kt < 4; ++kt) {
        int k0 = kt * 16;
        uint32_t a[4];
        LDSM4(a[0], a[1], a[2], a[3],
              sq + (uint32_t)((wm * 16 + a_r) * 72 + k0 + a_c) * 2u);
#pragma unroll
        for (int pp = 0; pp < 3; ++pp) {
            int nb = wn * 40 + pp * 16;
            uint32_t addr = (uint32_t)((nb + b_r) * 72 + k0 + b_c) * 2u;
            uint32_t r0, r1, r2, r3;
            LDSM4(r0, r1, r2, r3, kh + addr);
            uint32_t s0, s1, s2, s3;
            LDSM4(s0, s1, s2, s3, kl + addr);
            uint32_t bh0[2] = {r0, r1};
            uint32_t bl0[2] = {s0, s1};
            MMA16816(acc[pp * 2], a, bh0);
            MMA16816(acc[pp * 2], a, bl0);
            if (pp * 2 + 1 < 5) {
                uint32_t bh1[2] = {r2, r3};
                uint32_t bl1[2] = {s2, s3};
                MMA16816(acc[pp * 2 + 1], a, bh1);
                MMA16816(acc[pp * 2 + 1], a, bl1);
            }
        }
    }

    const int g = lane >> 2;
    const int t = lane & 3;
    if (wn == 1 && t == 0) {
        sNrm[wm * 16 + g]     = acc[3][0];
        sNrm[wm * 16 + g + 8] = acc[3][2];
    }
    __syncthreads();

    int r0 = wm * 16 + g;
    int r1 = r0 + 8;
    float inv0 = 1.f / (sNrm[r0] + EPSV);
    float inv1 = 1.f / (sNrm[r1] + EPSV);
    __half* o0 = g_attnh + (size_t)(b * SEQ + n0 + r0) * DIM + h * HDIM;
    __half* o1 = g_attnh + (size_t)(b * SEQ + n0 + r1) * DIM + h * HDIM;
#pragma unroll
    for (int lt = 0; lt < 5; ++lt) {
        int ncol = wn * 40 + lt * 8 + 2 * t;
        if (ncol < 64) {
            *(__half2*)(o0 + ncol) = __floats2half2_rn(acc[lt][0] * inv0, acc[lt][1] * inv0);
            *(__half2*)(o1 + ncol) = __floats2half2_rn(acc[lt][2] * inv1, acc[lt][3] * inv1);
        }
    }
}

// ---------------- launch ----------------------------------------------------
extern "C" void kernel_launch(void* const* d_in, const int* in_sizes, int n_in,
                              void* d_out, int out_size) {
    const float* x  = (const float*)d_in[0];
    const float* Wq = (const float*)d_in[1];
    const float* bq = (const float*)d_in[2];
    const float* Wk = (const float*)d_in[3];
    const float* bk = (const float*)d_in[4];
    const float* Wv = (const float*)d_in[5];
    const float* bv = (const float*)d_in[6];
    const float* Wo = (const float*)d_in[7];
    const float* bo = (const float*)d_in[8];
    float* out = (float*)d_out;

    cudaFuncSetAttribute(qkv_gemm_h, cudaFuncAttributeMaxDynamicSharedMemorySize, GEMM_SMEM);
    cudaFuncSetAttribute(out_gemm_h, cudaFuncAttributeMaxDynamicSharedMemorySize, GEMM_SMEM);

    // launch order: 6th launch (ncu -s 5 -c 1 target) = out_gemm_h
    conv_all<<<(XN4 + 4 * WN4 + 255) / 256, 256>>>(x, Wq, Wk, Wv, Wo);
    qkv_gemm_h<<<dim3(QKVLD / BN, MROWS / BM), 256, GEMM_SMEM>>>(bq, bk, bv);
    zero_state<<<1024, 256>>>();
    kv_state_h<<<dim3(64, 8), 128>>>();
    attn_epilogue_h<<<dim3(64, 64), 256>>>();
    out_gemm_h<<<dim3(DIM / BN, MROWS / BM), 256, GEMM_SMEM>>>(bo, out);
}

// round 15
// speedup vs baseline: 7.1142x; 1.0349x over previous
#include <cuda_runtime.h>
#include <cuda_fp16.h>
#include <cstdint>

#define BSZ   4
#define SEQ   4096
#define DIM   1024
#define NHEAD 16
#define HDIM  64
#define MROWS (BSZ * SEQ)
#define QKVLD 3072
#define EPSV  1e-6f

// ---- fp16 HMMA GEMM tiling: 128x128 CTA tile, BK=64, 3 stages, 2 CTAs/SM ---
#define BM 128
#define BN 128
#define BK 64
#define NCH (DIM / BK)              // 16 chunks
#define LDHB 144u                   // smem row pitch bytes (72 halves)
#define A_BYTES 18432u
#define STGB 36864u
#define GEMM_SMEM (3 * STGB)        // 110592B

#define XN4 (MROWS * DIM / 4)
#define WN4 (DIM * DIM / 4)

// ---------------- scratch (static device globals) ---------------------------
__device__ __half g_qkvh[(size_t)MROWS * QKVLD];  // Q|K|V half (phi applied to Q,K)
__device__ __half g_attnh[(size_t)MROWS * DIM];   // attention out (half)
__device__ __half g_xh[(size_t)MROWS * DIM];      // x in half
__device__ __half g_wh[4 * (size_t)DIM * DIM];    // Wq|Wk|Wv|Wo in half
__device__ float  g_kv[64 * 64 * 64];
__device__ float  g_z[64 * 64];

// ---------------- PTX helpers ------------------------------------------------
__device__ __forceinline__ uint32_t smem_u32(const void* p) {
    return (uint32_t)__cvta_generic_to_shared(p);
}

#define CP_ASYNC16(dst, src) \
    asm volatile("cp.async.cg.shared.global [%0], [%1], 16;" :: "r"(dst), "l"(src))
#define CP_COMMIT() asm volatile("cp.async.commit_group;" ::: "memory")
#define CP_WAIT_1() asm volatile("cp.async.wait_group 1;" ::: "memory")
#define CP_WAIT_0() asm volatile("cp.async.wait_group 0;" ::: "memory")

#define LDSM4(r0, r1, r2, r3, addr) \
    asm volatile("ldmatrix.sync.aligned.m8n8.x4.shared.b16 {%0,%1,%2,%3}, [%4];" \
                 : "=r"(r0), "=r"(r1), "=r"(r2), "=r"(r3) : "r"(addr))

#define LDSM4T(r0, r1, r2, r3, addr) \
    asm volatile("ldmatrix.sync.aligned.m8n8.x4.trans.shared.b16 {%0,%1,%2,%3}, [%4];" \
                 : "=r"(r0), "=r"(r1), "=r"(r2), "=r"(r3) : "r"(addr))

#define LDSM2T(r0, r1, addr) \
    asm volatile("ldmatrix.sync.aligned.m8n8.x2.trans.shared.b16 {%0,%1}, [%2];" \
                 : "=r"(r0), "=r"(r1) : "r"(addr))

#define MMA16816(d, a, b) \
    asm volatile("mma.sync.aligned.m16n8k16.row.col.f32.f16.f16.f32 " \
                 "{%0,%1,%2,%3}, {%4,%5,%6,%7}, {%8,%9}, {%0,%1,%2,%3};" \
                 : "+f"((d)[0]), "+f"((d)[1]), "+f"((d)[2]), "+f"((d)[3]) \
                 : "r"((a)[0]), "r"((a)[1]), "r"((a)[2]), "r"((a)[3]), \
                   "r"((b)[0]), "r"((b)[1]))

// ---------------- zero the accumulation state ------------------------------
__global__ void zero_state() {
    int i = blockIdx.x * blockDim.x + threadIdx.x;
    if (i < 64 * 64 * 64) g_kv[i] = 0.f;
    if (i < 64 * 64)      g_z[i]  = 0.f;
}

// ---------------- fused fp32 -> fp16 conversion (x + 4 weights) -------------
__global__ void conv_all(const float* __restrict__ x,
                         const float* __restrict__ Wq, const float* __restrict__ Wk,
                         const float* __restrict__ Wv, const float* __restrict__ Wo)
{
    int i = blockIdx.x * blockDim.x + threadIdx.x;
    if (i >= XN4 + 4 * WN4) return;
    const float* s;
    __half* d;
    int j;
    if (i < XN4) {
        s = x; d = g_xh; j = i;
    } else {
        int t = i - XN4;
        int w = t >> 18;
        j = t & (WN4 - 1);
        s = (w == 0) ? Wq : ((w == 1) ? Wk : ((w == 2) ? Wv : Wo));
        d = g_wh + (size_t)w * DIM * DIM;
    }
    float4 v = ((const float4*)s)[j];
    ((__half2*)d)[2 * j]     = __floats2half2_rn(v.x, v.y);
    ((__half2*)d)[2 * j + 1] = __floats2half2_rn(v.z, v.w);
}

// ---------------- stage loader (cp.async, BK=64) ----------------------------
__device__ __forceinline__ void load_stage_h(
    uint32_t sb, int chunk,
    const __half* __restrict__ Ag, const __half* __restrict__ Wg, int tid)
{
    const int k0 = chunk * BK;
#pragma unroll
    for (int i = 0; i < 8; ++i) {
        int s = tid + i * 256;
        int isB = (s >= 1024) ? 1 : 0;
        int t2 = s & 1023;
        int row = t2 >> 3;
        int seg = t2 & 7;
        const __half* src = (isB ? Wg : Ag) + (size_t)row * DIM + k0 + seg * 8;
        uint32_t dst = sb + (isB ? A_BYTES : 0u) + (uint32_t)row * LDHB + (uint32_t)seg * 16u;
        CP_ASYNC16(dst, src);
    }
    CP_COMMIT();
}

// ---------------- fp16 HMMA GEMM core (128x128, warp tile 64x32) ------------
__device__ __forceinline__ void gemm_h_core(
    const __half* __restrict__ Ag, const __half* __restrict__ Wg,
    const float* __restrict__ bias, void* Cg,
    int ldc, int isphi, int outhalf, __half* hsm)
{
    const int tid  = threadIdx.x;
    const int wid  = tid >> 5;
    const int lane = tid & 31;
    const int wm   = wid & 1;
    const int wn   = wid >> 1;

    const uint32_t sbase = smem_u32(hsm);

    const int a_r = lane & 15;
    const int a_c = (lane >> 4) * 8;
    const int b_r = (lane & 7) + ((lane >> 4) & 1) * 8;
    const int b_c = ((lane >> 3) & 1) * 8;

    float acc[4][4][4];
#pragma unroll
    for (int i = 0; i < 4; ++i)
#pragma unroll
        for (int j = 0; j < 4; ++j)
#pragma unroll
            for (int e = 0; e < 4; ++e) acc[i][j][e] = 0.f;

    load_stage_h(sbase + 0u * STGB, 0, Ag, Wg, tid);
    load_stage_h(sbase + 1u * STGB, 1, Ag, Wg, tid);

    for (int c = 0; c < NCH; ++c) {
        if (c + 2 < NCH) { CP_WAIT_1(); } else { CP_WAIT_0(); }
        __syncthreads();
        if (c + 2 < NCH)
            load_stage_h(sbase + (uint32_t)((c + 2) % 3) * STGB, c + 2, Ag, Wg, tid);

        const uint32_t As = sbase + (uint32_t)(c % 3) * STGB;
        const uint32_t Bs = As + A_BYTES;

#pragma unroll
        for (int ks = 0; ks < BK; ks += 16) {
            uint32_t a[4][4];
#pragma unroll
            for (int mb = 0; mb < 4; ++mb) {
                uint32_t addr = As + (uint32_t)(wm * 64 + mb * 16 + a_r) * LDHB
                              + (uint32_t)(ks + a_c) * 2u;
                LDSM4(a[mb][0], a[mb][1], a[mb][2], a[mb][3], addr);
            }
            uint32_t b[4][2];
#pragma unroll
            for (int p = 0; p < 2; ++p) {
                uint32_t addr = Bs + (uint32_t)(wn * 32 + p * 16 + b_r) * LDHB
                              + (uint32_t)(ks + b_c) * 2u;
                uint32_t r0, r1, r2, r3;
                LDSM4(r0, r1, r2, r3, addr);
                b[2 * p][0] = r0; b[2 * p][1] = r1;
                b[2 * p + 1][0] = r2; b[2 * p + 1][1] = r3;
            }
#pragma unroll
            for (int mb = 0; mb < 4; ++mb)
#pragma unroll
                for (int nb = 0; nb < 4; ++nb)
                    MMA16816(acc[mb][nb], a[mb], b[nb]);
        }
        __syncthreads();
    }

    const int g = lane >> 2;
    const int t = lane & 3;
#pragma unroll
    for (int mb = 0; mb < 4; ++mb) {
#pragma unroll
        for (int nb = 0; nb < 4; ++nb) {
            int col  = wn * 32 + nb * 8 + 2 * t;
            float b0 = bias[col];
            float b1 = bias[col + 1];
            int row0 = wm * 64 + mb * 16 + g;
            float v0 = acc[mb][nb][0] + b0;
            float v1 = acc[mb][nb][1] + b1;
            float v2 = acc[mb][nb][2] + b0;
            float v3 = acc[mb][nb][3] + b1;
            if (isphi) {
                v0 = (v0 > 0.f) ? (v0 + 1.f) : __expf(v0);
                v1 = (v1 > 0.f) ? (v1 + 1.f) : __expf(v1);
                v2 = (v2 > 0.f) ? (v2 + 1.f) : __expf(v2);
                v3 = (v3 > 0.f) ? (v3 + 1.f) : __expf(v3);
            }
            if (outhalf) {
                __half* C = (__half*)Cg;
                *(__half2*)(C + (size_t)row0 * ldc + col)       = __floats2half2_rn(v0, v1);
                *(__half2*)(C + (size_t)(row0 + 8) * ldc + col) = __floats2half2_rn(v2, v3);
            } else {
                float* C = (float*)Cg;
                *(float2*)(C + (size_t)row0 * ldc + col)       = make_float2(v0, v1);
                *(float2*)(C + (size_t)(row0 + 8) * ldc + col) = make_float2(v2, v3);
            }
        }
    }
}

// ---------------- GEMM entry points -----------------------------------------
__global__ __launch_bounds__(256, 2) void qkv_gemm_h(
    const float* __restrict__ bq, const float* __restrict__ bk,
    const float* __restrict__ bv)
{
    extern __shared__ __align__(16) __half hsm[];
    const int bn = blockIdx.x * BN;
    const int bm = blockIdx.y * BM;
    const int sel   = bn >> 10;
    const int wbase = bn & 1023;
    const float* bias = (sel == 0) ? bq : ((sel == 1) ? bk : bv);

    gemm_h_core(g_xh + (size_t)bm * DIM,
                g_wh + (size_t)sel * DIM * DIM + (size_t)wbase * DIM,
                bias + wbase,
                g_qkvh + (size_t)bm * QKVLD + bn,
                QKVLD, (sel < 2) ? 1 : 0, 1, hsm);
}

__global__ __launch_bounds__(256, 2) void out_gemm_h(
    const float* __restrict__ bo, float* __restrict__ out)
{
    extern __shared__ __align__(16) __half hsm[];
    const int bn = blockIdx.x * BN;
    const int bm = blockIdx.y * BM;

    gemm_h_core(g_attnh + (size_t)bm * DIM,
                g_wh + 3 * (size_t)DIM * DIM + (size_t)bn * DIM,
                bo + bn,
                out + (size_t)bm * DIM + bn,
                DIM, 0, 0, hsm);
}

// ---------------- KV state + Z via HMMA (double-buffered) -------------------
// KV[d,e] = sum_n K[n,d]*V[n,e]; Z[d] via ones-column e=64.
__global__ __launch_bounds__(128) void kv_state_h() {
    __shared__ __half Kt[2][64 * 72];
    __shared__ __half Vt[2][64 * 72 + 8];

    const int bh = blockIdx.x;
    const int b  = bh >> 4;
    const int h  = bh & 15;
    const int n0 = blockIdx.y * 512;

    const int tid  = threadIdx.x;
    const int wid  = tid >> 5;
    const int lane = tid & 31;

    // init V ext columns for both buffers (loads never touch cols 64-71)
    for (int u = tid; u < 512; u += 128) {
        int bf = u >> 8;
        int u2 = u & 255;
        int r  = u2 >> 2;
        int c2 = u2 & 3;
        __half2 v = (c2 == 0) ? __halves2half2(__float2half(1.f), __float2half(0.f))
                              : __halves2half2(__float2half(0.f), __float2half(0.f));
        *(__half2*)&Vt[bf][r * 72 + 64 + c2 * 2] = v;
    }
    __syncthreads();

    const __half* Kbase = g_qkvh + (size_t)(b * SEQ) * QKVLD + 1024 + h * HDIM;
    const __half* Vbase = g_qkvh + (size_t)(b * SEQ) * QKVLD + 2048 + h * HDIM;

    const int tA_r = (lane & 7) + ((lane >> 4) & 1) * 8;
    const int tA_c = ((lane >> 3) & 1) * 8;
    const int tB_r = (lane & 7) + ((lane >> 3) & 1) * 8;
    const int tB_c = ((lane >> 4) & 1) * 8;

    float acc[9][4];
#pragma unroll
    for (int i = 0; i < 9; ++i)
#pragma unroll
        for (int e = 0; e < 4; ++e) acc[i][e] = 0.f;

    // loader lambda-free: issue one 64-row tile into buffer bf
    const int l_isV = (tid >= 64) ? 1 : 0;       // 128 thr: 64 K-segs..., need 1024 segs
    // (issue loop handles mapping internally)

#define KV_LOAD(tile, bf) do { \
        const int _nb = n0 + (tile) * 64; \
        _Pragma("unroll") \
        for (int _i = 0; _i < 8; ++_i) { \
            int _s   = tid + _i * 128; \
            int _isV = (_s >= 512) ? 1 : 0; \
            int _s2  = _s & 511; \
            int _r   = _s2 >> 3; \
            int _seg = _s2 & 7; \
            const __half* _src = (_isV ? Vbase : Kbase) + (size_t)(_nb + _r) * QKVLD + _seg * 8; \
            uint32_t _dst = (_isV ? smem_u32(Vt[bf]) : smem_u32(Kt[bf])) \
                          + (uint32_t)_r * 144u + (uint32_t)_seg * 16u; \
            CP_ASYNC16(_dst, _src); \
        } \
        CP_COMMIT(); \
    } while (0)

    KV_LOAD(0, 0);

    for (int t = 0; t < 8; ++t) {
        if (t < 7) { KV_LOAD(t + 1, (t + 1) & 1); CP_WAIT_1(); }
        else       { CP_WAIT_0(); }
        __syncthreads();

        const uint32_t kb = smem_u32(Kt[t & 1]);
        const uint32_t vb = smem_u32(Vt[t & 1]);
#pragma unroll
        for (int k0 = 0; k0 < 64; k0 += 16) {
            uint32_t a[4];
            LDSM4T(a[0], a[1], a[2], a[3],
                   kb + (uint32_t)((k0 + tA_r) * 72 + wid * 16 + tA_c) * 2u);
#pragma unroll
            for (int p = 0; p < 4; ++p) {
                uint32_t r0, r1, r2, r3;
                LDSM4T(r0, r1, r2, r3,
                       vb + (uint32_t)((k0 + tB_r) * 72 + p * 16 + tB_c) * 2u);
                uint32_t b0[2] = {r0, r1};
                uint32_t b1[2] = {r2, r3};
                MMA16816(acc[2 * p], a, b0);
                MMA16816(acc[2 * p + 1], a, b1);
            }
            {
                uint32_t r0, r1;
                LDSM2T(r0, r1, vb + (uint32_t)((k0 + tB_r) * 72 + 64) * 2u);
                uint32_t bz[2] = {r0, r1};
                MMA16816(acc[8], a, bz);
            }
        }
        __syncthreads();
    }
#undef KV_LOAD
    (void)l_isV;

    const int g = lane >> 2;
    const int t = lane & 3;
    const int d0 = wid * 16 + g;
    const int d1 = d0 + 8;
    float* kvp = g_kv + (size_t)bh * 4096;
#pragma unroll
    for (int nb = 0; nb < 8; ++nb) {
        int e0 = nb * 8 + 2 * t;
        atomicAdd(&kvp[d0 * 64 + e0],     acc[nb][0]);
        atomicAdd(&kvp[d0 * 64 + e0 + 1], acc[nb][1]);
        atomicAdd(&kvp[d1 * 64 + e0],     acc[nb][2]);
        atomicAdd(&kvp[d1 * 64 + e0 + 1], acc[nb][3]);
    }
    if (t == 0) {
        atomicAdd(&g_z[bh * 64 + d0], acc[8][0]);
        atomicAdd(&g_z[bh * 64 + d1], acc[8][2]);
    }
}

// ---------------- attention epilogue: 128 rows/CTA, hi/lo KV + Z column -----
__global__ __launch_bounds__(256) void attn_epilogue_h() {
    __shared__ __half sQ[128 * 72];       // [n][d]
    __shared__ __half sKVh[96 * 72];      // [e_ext][d]
    __shared__ __half sKVl[96 * 72];
    __shared__ float  sNrm[128];

    const int bh = blockIdx.x;
    const int b  = bh >> 4;
    const int h  = bh & 15;
    const int n0 = blockIdx.y * 128;
    const int tid  = threadIdx.x;
    const int wid  = tid >> 5;
    const int lane = tid & 31;

    // stage Q: 128 rows x 8 segs = 1024 segs
    const __half* Qb = g_qkvh + (size_t)(b * SEQ + n0) * QKVLD + h * HDIM;
#pragma unroll
    for (int i = 0; i < 4; ++i) {
        int idx = tid + i * 256;
        int r   = idx >> 3;
        int seg = idx & 7;
        *(uint4*)&sQ[r * 72 + seg * 8] = *(const uint4*)(Qb + (size_t)r * QKVLD + seg * 8);
    }
    // stage KV transposed, hi/lo split
    const float* KVb = g_kv + (size_t)bh * 4096;
#pragma unroll
    for (int i = 0; i < 16; ++i) {
        int idx = tid + i * 256;
        int d = idx >> 6;
        int e = idx & 63;
        float v = KVb[idx];
        __half hi = __float2half_rn(v);
        sKVh[e * 72 + d] = hi;
        sKVl[e * 72 + d] = __float2half_rn(v - __half2float(hi));
    }
    if (tid < 64) {
        float z = g_z[bh * 64 + tid];
        __half hi = __float2half_rn(z);
        sKVh[64 * 72 + tid] = hi;
        sKVl[64 * 72 + tid] = __float2half_rn(z - __half2float(hi));
    }
    __syncthreads();

    const int wm = wid & 3;               // row sub-block within 64-row half
    const int wn = wid >> 2;              // col strip (40 cols)
    const int a_r = lane & 15;
    const int a_c = (lane >> 4) * 8;
    const int b_r = (lane & 7) + ((lane >> 4) & 1) * 8;
    const int b_c = ((lane >> 3) & 1) * 8;

    float acc[2][5][4];
#pragma unroll
    for (int rb = 0; rb < 2; ++rb)
#pragma unroll
        for (int i = 0; i < 5; ++i)
#pragma unroll
            for (int e = 0; e < 4; ++e) acc[rb][i][e] = 0.f;

    const uint32_t sq = smem_u32(sQ);
    const uint32_t kh = smem_u32(sKVh);
    const uint32_t kl = smem_u32(sKVl);

#pragma unroll
    for (int kt = 0; kt < 4; ++kt) {
        int k0 = kt * 16;
        uint32_t a[2][4];
#pragma unroll
        for (int rb = 0; rb < 2; ++rb)
            LDSM4(a[rb][0], a[rb][1], a[rb][2], a[rb][3],
                  sq + (uint32_t)((rb * 64 + wm * 16 + a_r) * 72 + k0 + a_c) * 2u);
#pragma unroll
        for (int pp = 0; pp < 3; ++pp) {
            int nb = wn * 40 + pp * 16;
            uint32_t addr = (uint32_t)((nb + b_r) * 72 + k0 + b_c) * 2u;
            uint32_t r0, r1, r2, r3;
            LDSM4(r0, r1, r2, r3, kh + addr);
            uint32_t s0, s1, s2, s3;
            LDSM4(s0, s1, s2, s3, kl + addr);
            uint32_t bh0[2] = {r0, r1};
            uint32_t bl0[2] = {s0, s1};
            uint32_t bh1[2] = {r2, r3};
            uint32_t bl1[2] = {s2, s3};
#pragma unroll
            for (int rb = 0; rb < 2; ++rb) {
                MMA16816(acc[rb][pp * 2], a[rb], bh0);
                MMA16816(acc[rb][pp * 2], a[rb], bl0);
                if (pp * 2 + 1 < 5) {
                    MMA16816(acc[rb][pp * 2 + 1], a[rb], bh1);
                    MMA16816(acc[rb][pp * 2 + 1], a[rb], bl1);
                }
            }
        }
    }

    const int g = lane >> 2;
    const int t = lane & 3;
    if (wn == 1 && t == 0) {
#pragma unroll
        for (int rb = 0; rb < 2; ++rb) {
            sNrm[rb * 64 + wm * 16 + g]     = acc[rb][3][0];
            sNrm[rb * 64 + wm * 16 + g + 8] = acc[rb][3][2];
        }
    }
    __syncthreads();

#pragma unroll
    for (int rb = 0; rb < 2; ++rb) {
        int r0 = rb * 64 + wm * 16 + g;
        int r1 = r0 + 8;
        float inv0 = 1.f / (sNrm[r0] + EPSV);
        float inv1 = 1.f / (sNrm[r1] + EPSV);
        __half* o0 = g_attnh + (size_t)(b * SEQ + n0 + r0) * DIM + h * HDIM;
        __half* o1 = g_attnh + (size_t)(b * SEQ + n0 + r1) * DIM + h * HDIM;
#pragma unroll
        for (int lt = 0; lt < 5; ++lt) {
            int ncol = wn * 40 + lt * 8 + 2 * t;
            if (ncol < 64) {
                *(__half2*)(o0 + ncol) = __floats2half2_rn(acc[rb][lt][0] * inv0,
                                                           acc[rb][lt][1] * inv0);
                *(__half2*)(o1 + ncol) = __floats2half2_rn(acc[rb][lt][2] * inv1,
                                                           acc[rb][lt][3] * inv1);
            }
        }
    }
}

// ---------------- launch ----------------------------------------------------
extern "C" void kernel_launch(void* const* d_in, const int* in_sizes, int n_in,
                              void* d_out, int out_size) {
    const float* x  = (const float*)d_in[0];
    const float* Wq = (const float*)d_in[1];
    const float* bq = (const float*)d_in[2];
    const float* Wk = (const float*)d_in[3];
    const float* bk = (const float*)d_in[4];
    const float* Wv = (const float*)d_in[5];
    const float* bv = (const float*)d_in[6];
    const float* Wo = (const float*)d_in[7];
    const float* bo = (const float*)d_in[8];
    float* out = (float*)d_out;

    cudaFuncSetAttribute(qkv_gemm_h, cudaFuncAttributeMaxDynamicSharedMemorySize, GEMM_SMEM);
    cudaFuncSetAttribute(out_gemm_h, cudaFuncAttributeMaxDynamicSharedMemorySize, GEMM_SMEM);

    conv_all<<<(XN4 + 4 * WN4 + 255) / 256, 256>>>(x, Wq, Wk, Wv, Wo);
    qkv_gemm_h<<<dim3(QKVLD / BN, MROWS / BM), 256, GEMM_SMEM>>>(bq, bk, bv);
    zero_state<<<1024, 256>>>();
    kv_state_h<<<dim3(64, 8), 128>>>();
    attn_epilogue_h<<<dim3(64, 32), 256>>>();
    out_gemm_h<<<dim3(DIM / BN, MROWS / BM), 256, GEMM_SMEM>>>(bo, out);
}